// round 9
// baseline (speedup 1.0000x reference)
#include <cuda_runtime.h>
#include <cuda_bf16.h>
#include <math.h>
#include <stdint.h>

#define Bv   8
#define Cv   768
#define Hv   28
#define Wv   28
#define Gv   6
#define GCv  128
#define NHv  12
#define HCv  64
#define Sv   784
#define Nv   (Bv * Sv)      // 6272
#define SCALEv 0.125f
#define EPSv 1e-5f
#define PADE 4096

typedef long long ll;

// ---------------- scratch (device globals; no allocation) ----------------
__device__ float g_q2 [Cv * Nv];                       // (768, 6272) fp32 (offset path)
__device__ float g_grid[Bv * Gv * Sv * 2];
__device__ float g_rsum[Bv * NHv * Sv];                // softmax row sums

__device__ __nv_bfloat16 g_qh [Cv * Nv + PADE], g_ql [Cv * Nv + PADE];   // (C, Nv)
__device__ __nv_bfloat16 g_kh [Cv * Nv + PADE], g_kl [Cv * Nv + PADE];
__device__ __nv_bfloat16 g_vh [Cv * Nv + PADE], g_vl [Cv * Nv + PADE];
__device__ __nv_bfloat16 g_x1h [Nv * Cv], g_x1l [Nv * Cv];               // (Nv, C)
__device__ __nv_bfloat16 g_xsth[Nv * Cv], g_xstl[Nv * Cv];
__device__ __nv_bfloat16 g_avth[Nv * Cv], g_avtl[Nv * Cv];
__device__ __nv_bfloat16 g_wqh [Cv * Cv], g_wql [Cv * Cv];
__device__ __nv_bfloat16 g_wkh [Cv * Cv], g_wkl [Cv * Cv];
__device__ __nv_bfloat16 g_wvh [Cv * Cv], g_wvl [Cv * Cv];
__device__ __nv_bfloat16 g_woh [Cv * Cv], g_wol [Cv * Cv];

// ======================= PTX helpers (sm_80-portable) =====================
__device__ __forceinline__ uint32_t smem_u32(const void* p) {
    uint32_t a;
    asm("{ .reg .u64 t; cvta.to.shared.u64 t, %1; cvt.u32.u64 %0, t; }" : "=r"(a) : "l"(p));
    return a;
}
__device__ __forceinline__ void cpa16(uint32_t dst, const void* src) {
    asm volatile("cp.async.cg.shared.global [%0], [%1], 16;" :: "r"(dst), "l"(src));
}
#define CP_COMMIT() asm volatile("cp.async.commit_group;" ::: "memory")
#define CP_WAIT1()  asm volatile("cp.async.wait_group 1;" ::: "memory")
#define CP_WAIT0()  asm volatile("cp.async.wait_group 0;" ::: "memory")

__device__ __forceinline__ void ldsm4(uint32_t* r, uint32_t addr) {
    asm volatile("ldmatrix.sync.aligned.m8n8.x4.shared.b16 {%0,%1,%2,%3}, [%4];"
        : "=r"(r[0]), "=r"(r[1]), "=r"(r[2]), "=r"(r[3]) : "r"(addr));
}
__device__ __forceinline__ void ldsm4t(uint32_t* r, uint32_t addr) {
    asm volatile("ldmatrix.sync.aligned.m8n8.x4.trans.shared.b16 {%0,%1,%2,%3}, [%4];"
        : "=r"(r[0]), "=r"(r[1]), "=r"(r[2]), "=r"(r[3]) : "r"(addr));
}
__device__ __forceinline__ void mma16816(float* c, const uint32_t* a, const uint32_t* b) {
    asm volatile(
        "mma.sync.aligned.m16n8k16.row.col.f32.bf16.bf16.f32 "
        "{%0,%1,%2,%3}, {%4,%5,%6,%7}, {%8,%9}, {%0,%1,%2,%3};"
        : "+f"(c[0]), "+f"(c[1]), "+f"(c[2]), "+f"(c[3])
        : "r"(a[0]), "r"(a[1]), "r"(a[2]), "r"(a[3]), "r"(b[0]), "r"(b[1]));
}
__device__ __forceinline__ void store_hilo(__nv_bfloat16* Hp, __nv_bfloat16* Lp,
                                           ll idx, float a, float b) {
    const __nv_bfloat16 ha = __float2bfloat16(a), hb = __float2bfloat16(b);
    __nv_bfloat162 hv; hv.x = ha; hv.y = hb;
    *(__nv_bfloat162*)(Hp + idx) = hv;
    __nv_bfloat162 lv;
    lv.x = __float2bfloat16(a - __bfloat162float(ha));
    lv.y = __float2bfloat16(b - __bfloat162float(hb));
    *(__nv_bfloat162*)(Lp + idx) = lv;
}

// =========================================================================
// bf16x3 warp-MMA GEMM (dual-set via blockIdx.z):
//   C[M x N] = A(MxK) . B(NxK)^T (+bias_m +bias_n)
// =========================================================================
#define KC       32
#define TPAD     40
#define TILE_B   (128 * TPAD * 2)
#define STAGE_B  (4 * TILE_B)
#define MMA_SMEM (2 * STAGE_B)

__global__ void __launch_bounds__(256, 2)
mma_gemm(const __nv_bfloat16* __restrict__ Ah, const __nv_bfloat16* __restrict__ Al,
         const __nv_bfloat16* __restrict__ Ah2, const __nv_bfloat16* __restrict__ Al2,
         const __nv_bfloat16* __restrict__ Bh, const __nv_bfloat16* __restrict__ Bl,
         float* __restrict__ Cf,
         __nv_bfloat16* __restrict__ Chi, __nv_bfloat16* __restrict__ Clo,
         __nv_bfloat16* __restrict__ Chi2, __nv_bfloat16* __restrict__ Clo2,
         int K, int ldc,
         const float* __restrict__ bias_m, const float* __restrict__ bias_m2,
         const float* __restrict__ bias_n)
{
    if (blockIdx.z == 1) {
        Ah = Ah2; Al = Al2; Chi = Chi2; Clo = Clo2; bias_m = bias_m2; Cf = nullptr;
    }
    extern __shared__ char smem[];
    const uint32_t sb = smem_u32(smem);
    const int tid = threadIdx.x;
    const int wid = tid >> 5, lane = tid & 31;

    const int m0 = blockIdx.y * 128;
    const int n0 = blockIdx.x * 128;

    const __nv_bfloat16* srcs[4] = {
        Ah + (ll)m0 * K, Al + (ll)m0 * K,
        Bh + (ll)n0 * K, Bl + (ll)n0 * K };

    const int NCk = K / KC;

    float acc[2][8][4];
#pragma unroll
    for (int i = 0; i < 2; i++)
#pragma unroll
        for (int j = 0; j < 8; j++)
#pragma unroll
            for (int r = 0; r < 4; r++) acc[i][j][r] = 0.f;

    auto issue = [&](int c) {
        const uint32_t st = sb + (uint32_t)(c & 1) * STAGE_B;
        const ll kb = (ll)c * KC;
#pragma unroll
        for (int t = 0; t < 4; t++) {
            const __nv_bfloat16* src = srcs[t];
            const uint32_t tb = st + t * TILE_B;
#pragma unroll
            for (int it = 0; it < 2; it++) {
                const int idx = tid + it * 256;
                const int row = idx >> 2;
                const int q   = idx & 3;
                cpa16(tb + row * 80 + q * 16, src + (ll)row * K + kb + q * 8);
            }
        }
    };

    issue(0); CP_COMMIT();

    const int wm = (wid & 3) * 32;
    const int wn = (wid >> 2) * 64;
    const int rsel = lane & 7;
    const int aRow = wm + rsel + ((lane >> 3) & 1) * 8;
    const int aColB = ((lane >> 4) & 1) * 16;
    const int bRow = wn + rsel + ((lane >> 4) & 1) * 8;
    const int bColB = ((lane >> 3) & 1) * 16;

    for (int c = 0; c < NCk; c++) {
        if (c + 1 < NCk) issue(c + 1);
        CP_COMMIT();
        CP_WAIT1();
        __syncthreads();

        const uint32_t st = sb + (uint32_t)(c & 1) * STAGE_B;
#pragma unroll
        for (int kst = 0; kst < 2; kst++) {
            uint32_t ah[2][4], al[2][4];
#pragma unroll
            for (int mf = 0; mf < 2; mf++) {
                const uint32_t ra = st + (aRow + mf * 16) * 80 + kst * 32 + aColB;
                ldsm4(ah[mf], ra);
                ldsm4(al[mf], ra + TILE_B);
            }
            uint32_t bh[8][2], bl[8][2];
#pragma unroll
            for (int nf2 = 0; nf2 < 4; nf2++) {
                const uint32_t rb = st + 2 * TILE_B + (bRow + nf2 * 16) * 80 + kst * 32 + bColB;
                uint32_t t4[4];
                ldsm4(t4, rb);
                bh[nf2 * 2][0] = t4[0]; bh[nf2 * 2][1] = t4[1];
                bh[nf2 * 2 + 1][0] = t4[2]; bh[nf2 * 2 + 1][1] = t4[3];
                ldsm4(t4, rb + TILE_B);
                bl[nf2 * 2][0] = t4[0]; bl[nf2 * 2][1] = t4[1];
                bl[nf2 * 2 + 1][0] = t4[2]; bl[nf2 * 2 + 1][1] = t4[3];
            }
#pragma unroll
            for (int mf = 0; mf < 2; mf++)
#pragma unroll
                for (int nf = 0; nf < 8; nf++) {
                    mma16816(acc[mf][nf], ah[mf], bh[nf]);
                    mma16816(acc[mf][nf], ah[mf], bl[nf]);
                    mma16816(acc[mf][nf], al[mf], bh[nf]);
                }
        }
        __syncthreads();
    }

#pragma unroll
    for (int mf = 0; mf < 2; mf++) {
        const int r0 = m0 + wm + mf * 16 + (lane >> 2);
        const int r1 = r0 + 8;
        const float bm0 = bias_m ? __ldg(&bias_m[r0]) : 0.f;
        const float bm1 = bias_m ? __ldg(&bias_m[r1]) : 0.f;
#pragma unroll
        for (int nf = 0; nf < 8; nf++) {
            const int col = n0 + wn + nf * 8 + (lane & 3) * 2;
            float bn0 = 0.f, bn1 = 0.f;
            if (bias_n) { bn0 = __ldg(&bias_n[col]); bn1 = __ldg(&bias_n[col + 1]); }
            const float* a = acc[mf][nf];
            const float v00 = a[0] + bm0 + bn0, v01 = a[1] + bm0 + bn1;
            const float v10 = a[2] + bm1 + bn0, v11 = a[3] + bm1 + bn1;
            const ll i0 = (ll)r0 * ldc + col;
            const ll i1 = (ll)r1 * ldc + col;
            if (Cf) {
                float2 f0; f0.x = v00; f0.y = v01; *(float2*)&Cf[i0] = f0;
                float2 f1; f1.x = v10; f1.y = v11; *(float2*)&Cf[i1] = f1;
            }
            if (Chi) {
                store_hilo(Chi, Clo, i0, v00, v01);
                store_hilo(Chi, Clo, i1, v10, v11);
            }
        }
    }
}

// =========================================================================
// fp32 -> bf16 hi/lo split (single) and 4-way weight split
// =========================================================================
__global__ __launch_bounds__(256)
void split_bf16(const float* __restrict__ in, __nv_bfloat16* __restrict__ hi,
                __nv_bfloat16* __restrict__ lo, int n)
{
    const int i = blockIdx.x * 256 + threadIdx.x;
    if (i < n) {
        const float x = in[i];
        const __nv_bfloat16 h = __float2bfloat16(x);
        hi[i] = h;
        lo[i] = __float2bfloat16(x - __bfloat162float(h));
    }
}

__global__ __launch_bounds__(256)
void split4_bf16(const float* __restrict__ w0, const float* __restrict__ w1,
                 const float* __restrict__ w2, const float* __restrict__ w3,
                 __nv_bfloat16* __restrict__ h0, __nv_bfloat16* __restrict__ l0,
                 __nv_bfloat16* __restrict__ h1, __nv_bfloat16* __restrict__ l1,
                 __nv_bfloat16* __restrict__ h2, __nv_bfloat16* __restrict__ l2,
                 __nv_bfloat16* __restrict__ h3, __nv_bfloat16* __restrict__ l3,
                 int n)
{
    const int i = blockIdx.x * 256 + threadIdx.x;
    if (i >= n) return;
    const int s = blockIdx.y;
    const float* in = (s == 0) ? w0 : (s == 1) ? w1 : (s == 2) ? w2 : w3;
    __nv_bfloat16* hi = (s == 0) ? h0 : (s == 1) ? h1 : (s == 2) ? h2 : h3;
    __nv_bfloat16* lo = (s == 0) ? l0 : (s == 1) ? l1 : (s == 2) ? l2 : l3;
    const float x = in[i];
    const __nv_bfloat16 h = __float2bfloat16(x);
    hi[i] = h;
    lo[i] = __float2bfloat16(x - __bfloat162float(h));
}

// =========================================================================
// Logits (Q-resident, K-streamed): one CTA per (bh, 128-row i-tile).
// =========================================================================
#define LROWB 272
#define LT    17408
#define LSK   (2 * LT)
#define LSMEM (6 * LT)

__global__ void __launch_bounds__(256, 1)
logits_mma(const __nv_bfloat16* __restrict__ qh, const __nv_bfloat16* __restrict__ ql,
           const __nv_bfloat16* __restrict__ kh, const __nv_bfloat16* __restrict__ kl,
           float* __restrict__ attn, float* __restrict__ rsum)
{
    extern __shared__ char smem[];
    __shared__ float srow[128];
    const uint32_t sb = smem_u32(smem);
    const int tid = threadIdx.x;
    const int wid = tid >> 5, lane = tid & 31;
    const int bh = blockIdx.y, b = bh / NHv, h = bh % NHv;
    const int i0 = blockIdx.x * 128;

    if (tid < 128) srow[tid] = 0.f;

    const ll off = (ll)(h * HCv) * Nv + (ll)b * Sv;
    const __nv_bfloat16* q0 = qh + off + i0;
    const __nv_bfloat16* q1 = ql + off + i0;
    const __nv_bfloat16* k0 = kh + off;
    const __nv_bfloat16* k1 = kl + off;

#pragma unroll
    for (int it = 0; it < 4; it++) {
        const int idx = tid + it * 256;
        const int row = idx >> 4, q = idx & 15;
        cpa16(sb + row * LROWB + q * 16, q0 + (ll)row * Nv + q * 8);
        cpa16(sb + LT + row * LROWB + q * 16, q1 + (ll)row * Nv + q * 8);
    }
    CP_COMMIT();

    auto issueK = [&](int jc) {
        const uint32_t st = sb + LSK + (uint32_t)(jc & 1) * (2 * LT);
        const ll jb = (ll)jc * 128;
#pragma unroll
        for (int it = 0; it < 4; it++) {
            const int idx = tid + it * 256;
            const int row = idx >> 4, q = idx & 15;
            const ll go = (ll)row * Nv + jb + q * 8;
            cpa16(st + row * LROWB + q * 16, k0 + go);
            cpa16(st + LT + row * LROWB + q * 16, k1 + go);
        }
    };
    issueK(0); CP_COMMIT();

    const int wm = (wid & 3) * 32;
    const int wn = (wid >> 2) * 64;
    const int arowk = (lane & 7) + ((lane >> 4) & 1) * 8;
    const int acolm = wm + ((lane >> 3) & 1) * 8;
    const int browk = (lane & 7) + ((lane >> 3) & 1) * 8;
    const int bcoln = wn + ((lane >> 4) & 1) * 8;
    const int cb2 = (lane & 3) * 2;

    float* Cp = attn + (ll)bh * Sv * Sv;
    float rs[2][2] = {{0.f, 0.f}, {0.f, 0.f}};

    for (int jc = 0; jc < 7; jc++) {
        if (jc + 1 < 7) { issueK(jc + 1); CP_COMMIT(); CP_WAIT1(); }
        else           { CP_WAIT0(); }
        __syncthreads();

        const uint32_t sKh = sb + LSK + (uint32_t)(jc & 1) * (2 * LT);

        float acc[2][8][4];
#pragma unroll
        for (int i = 0; i < 2; i++)
#pragma unroll
            for (int j = 0; j < 8; j++)
#pragma unroll
                for (int r = 0; r < 4; r++) acc[i][j][r] = 0.f;

#pragma unroll
        for (int kst = 0; kst < 4; kst++) {
            uint32_t ah[2][4], al[2][4];
#pragma unroll
            for (int mf = 0; mf < 2; mf++) {
                const uint32_t ra = sb + (kst * 16 + arowk) * LROWB + (acolm + mf * 16) * 2;
                ldsm4t(ah[mf], ra);
                ldsm4t(al[mf], ra + LT);
            }
            uint32_t bhf[8][2], blf[8][2];
#pragma unroll
            for (int nf2 = 0; nf2 < 4; nf2++) {
                const uint32_t rb = sKh + (kst * 16 + browk) * LROWB + (bcoln + nf2 * 16) * 2;
                uint32_t t4[4];
                ldsm4t(t4, rb);
                bhf[nf2 * 2][0] = t4[0]; bhf[nf2 * 2][1] = t4[1];
                bhf[nf2 * 2 + 1][0] = t4[2]; bhf[nf2 * 2 + 1][1] = t4[3];
                ldsm4t(t4, rb + LT);
                blf[nf2 * 2][0] = t4[0]; blf[nf2 * 2][1] = t4[1];
                blf[nf2 * 2 + 1][0] = t4[2]; blf[nf2 * 2 + 1][1] = t4[3];
            }
#pragma unroll
            for (int mf = 0; mf < 2; mf++)
#pragma unroll
                for (int nf = 0; nf < 8; nf++) {
                    mma16816(acc[mf][nf], ah[mf], bhf[nf]);
                    mma16816(acc[mf][nf], ah[mf], blf[nf]);
                    mma16816(acc[mf][nf], al[mf], bhf[nf]);
                }
        }

        const int j0 = jc * 128;
#pragma unroll
        for (int mf = 0; mf < 2; mf++) {
            const int r0 = i0 + wm + mf * 16 + (lane >> 2);
            const int r1 = r0 + 8;
#pragma unroll
            for (int nf = 0; nf < 8; nf++) {
                const int col = j0 + wn + nf * 8 + cb2;
                if (col >= Sv) continue;
                const float* a = acc[mf][nf];
                if (r0 < Sv) {
                    float2 f;
                    f.x = __expf(a[0] * SCALEv);
                    f.y = __expf(a[1] * SCALEv);
                    *(float2*)&Cp[(ll)r0 * Sv + col] = f;
                    rs[mf][0] += f.x + f.y;
                }
                if (r1 < Sv) {
                    float2 f;
                    f.x = __expf(a[2] * SCALEv);
                    f.y = __expf(a[3] * SCALEv);
                    *(float2*)&Cp[(ll)r1 * Sv + col] = f;
                    rs[mf][1] += f.x + f.y;
                }
            }
        }
        __syncthreads();
    }

#pragma unroll
    for (int mf = 0; mf < 2; mf++) {
        float s0 = rs[mf][0], s1 = rs[mf][1];
        s0 += __shfl_xor_sync(0xffffffffu, s0, 1);
        s0 += __shfl_xor_sync(0xffffffffu, s0, 2);
        s1 += __shfl_xor_sync(0xffffffffu, s1, 1);
        s1 += __shfl_xor_sync(0xffffffffu, s1, 2);
        if ((lane & 3) == 0) {
            const int lr = wm + mf * 16 + (lane >> 2);
            atomicAdd(&srow[lr], s0);
            atomicAdd(&srow[lr + 8], s1);
        }
    }
    __syncthreads();
    if (tid < 128 && i0 + tid < Sv)
        rsum[(ll)bh * Sv + i0 + tid] = srow[tid];
}

// =========================================================================
// AV + softmax-normalize (pipelined)
// =========================================================================
#define AVROWB 80
#define AV_A_H   0
#define AV_A_L   10240
#define AV_B     20480
#define AV_SMEMB (20480 + 2 * 10240)

__global__ void __launch_bounds__(256, 1)
av_mma(float* __restrict__ attn, const float* __restrict__ rsum,
       const __nv_bfloat16* __restrict__ vh, const __nv_bfloat16* __restrict__ vl,
       __nv_bfloat16* __restrict__ avth, __nv_bfloat16* __restrict__ avtl)
{
    __shared__ char smc[AV_SMEMB];
    __shared__ float sm_inv[128];
    const uint32_t sb = smem_u32(smc);

    const int tid = threadIdx.x;
    const int wid = tid >> 5, lane = tid & 31;
    const int bh = blockIdx.y, b = bh / NHv, h = bh % NHv;
    const int n0 = blockIdx.x * 128;

    float* Ap = attn + (ll)bh * Sv * Sv;
    const __nv_bfloat16* vbh = vh + (ll)(h * HCv) * Nv + (ll)b * Sv;
    const __nv_bfloat16* vbl = vl + (ll)(h * HCv) * Nv + (ll)b * Sv;

    if (tid < 128) {
        const int gn = n0 + tid;
        sm_inv[tid] = (gn < Sv) ? (1.f / rsum[(ll)bh * Sv + gn]) : 0.f;
    }
    __syncthreads();

    float acc[2][4][4];
#pragma unroll
    for (int i = 0; i < 2; i++)
#pragma unroll
        for (int j = 0; j < 4; j++)
#pragma unroll
            for (int r = 0; r < 4; r++) acc[i][j][r] = 0.f;

    const int wm = (wid & 3) * 32;
    const int wn = (wid >> 2) * 32;
    const int rsel = lane & 7;
    const int aRow = wm + rsel + ((lane >> 3) & 1) * 8;
    const int aColB = ((lane >> 4) & 1) * 16;
    const int bRow = wn + rsel + ((lane >> 4) & 1) * 8;
    const int bColB = ((lane >> 3) & 1) * 16;

    const int vrow = tid >> 2;
    const int vq   = tid & 3;

    float4 areg[4];

    auto issueB = [&](int kc) {
        const int kb = kc * 32;
        const uint32_t bb = sb + AV_B + (uint32_t)(kc & 1) * 10240;
        cpa16(bb + vrow * AVROWB + vq * 16, vbh + (ll)vrow * Nv + kb + vq * 8);
        cpa16(bb + 5120 + vrow * AVROWB + vq * 16, vbl + (ll)vrow * Nv + kb + vq * 8);
    };
    auto loadA = [&](int kc) {
        const int kb = kc * 32;
#pragma unroll
        for (int it = 0; it < 4; it++) {
            const int idx4 = tid + it * 256;
            const int row = idx4 >> 3;
            const int qq  = idx4 & 7;
            const int gn = n0 + row;
            const int gk = kb + qq * 4;
            areg[it] = make_float4(0.f, 0.f, 0.f, 0.f);
            if (gn < Sv && gk < Sv)
                areg[it] = *(const float4*)&Ap[(ll)gn * Sv + gk];
        }
    };

    issueB(0); CP_COMMIT();
    loadA(0);

    for (int kc = 0; kc < 25; kc++) {
        const int kb = kc * 32;
#pragma unroll
        for (int it = 0; it < 4; it++) {
            const int idx4 = tid + it * 256;
            const int row = idx4 >> 3;
            const int qq  = idx4 & 7;
            const int gn = n0 + row;
            const int gk = kb + qq * 4;
            float4 v = areg[it];
            const float inv = sm_inv[row];
            v.x *= inv; v.y *= inv; v.z *= inv; v.w *= inv;
            if (gn < Sv && gk < Sv) *(float4*)&Ap[(ll)gn * Sv + gk] = v;
            const __nv_bfloat16 h0 = __float2bfloat16(v.x), h1 = __float2bfloat16(v.y);
            const __nv_bfloat16 h2 = __float2bfloat16(v.z), h3 = __float2bfloat16(v.w);
            __nv_bfloat162 p01, p23, q01, q23;
            p01.x = h0; p01.y = h1; p23.x = h2; p23.y = h3;
            q01.x = __float2bfloat16(v.x - __bfloat162float(h0));
            q01.y = __float2bfloat16(v.y - __bfloat162float(h1));
            q23.x = __float2bfloat16(v.z - __bfloat162float(h2));
            q23.y = __float2bfloat16(v.w - __bfloat162float(h3));
            uint2 hw, lw;
            hw.x = *(uint32_t*)&p01; hw.y = *(uint32_t*)&p23;
            lw.x = *(uint32_t*)&q01; lw.y = *(uint32_t*)&q23;
            *(uint2*)(smc + AV_A_H + row * AVROWB + qq * 8) = hw;
            *(uint2*)(smc + AV_A_L + row * AVROWB + qq * 8) = lw;
        }
        if (kc + 1 < 25) {
            issueB(kc + 1); CP_COMMIT();
            loadA(kc + 1);
            CP_WAIT1();
        } else {
            CP_WAIT0();
        }
        __syncthreads();

        const uint32_t sBh = sb + AV_B + (uint32_t)(kc & 1) * 10240;
        const uint32_t sAh = sb + AV_A_H;
#pragma unroll
        for (int kst = 0; kst < 2; kst++) {
            uint32_t ah[2][4], al[2][4];
#pragma unroll
            for (int mf = 0; mf < 2; mf++) {
                const uint32_t ra = sAh + (aRow + mf * 16) * AVROWB + kst * 32 + aColB;
                ldsm4(ah[mf], ra);
                ldsm4(al[mf], ra + (AV_A_L - AV_A_H));
            }
            uint32_t bhf[4][2], blf[4][2];
#pragma unroll
            for (int nf2 = 0; nf2 < 2; nf2++) {
                const uint32_t rb = sBh + (bRow + nf2 * 16) * AVROWB + kst * 32 + bColB;
                uint32_t t4[4];
                ldsm4(t4, rb);
                bhf[nf2 * 2][0] = t4[0]; bhf[nf2 * 2][1] = t4[1];
                bhf[nf2 * 2 + 1][0] = t4[2]; bhf[nf2 * 2 + 1][1] = t4[3];
                ldsm4(t4, rb + 5120);
                blf[nf2 * 2][0] = t4[0]; blf[nf2 * 2][1] = t4[1];
                blf[nf2 * 2 + 1][0] = t4[2]; blf[nf2 * 2 + 1][1] = t4[3];
            }
#pragma unroll
            for (int mf = 0; mf < 2; mf++)
#pragma unroll
                for (int nf = 0; nf < 4; nf++) {
                    mma16816(acc[mf][nf], ah[mf], bhf[nf]);
                    mma16816(acc[mf][nf], ah[mf], blf[nf]);
                    mma16816(acc[mf][nf], al[mf], bhf[nf]);
                }
        }
        __syncthreads();
    }

#pragma unroll
    for (int mf = 0; mf < 2; mf++) {
        const int r0 = n0 + wm + mf * 16 + (lane >> 2);
        const int r1 = r0 + 8;
#pragma unroll
        for (int nf = 0; nf < 4; nf++) {
            const int cold = wn + nf * 8 + (lane & 3) * 2;
            const ll colg = (ll)h * HCv + cold;
            const float* a = acc[mf][nf];
            if (r0 < Sv)
                store_hilo(avth, avtl, ((ll)b * Sv + r0) * Cv + colg, a[0], a[1]);
            if (r1 < Sv)
                store_hilo(avth, avtl, ((ll)b * Sv + r1) * Cv + colg, a[2], a[3]);
        }
    }
}

// =========================================================================
// Fused dwconv5x5 -> LN -> GELU -> offset proj -> sampling coords
// Conv: register sliding-window; thread = (channel, half-row of 14 outputs).
// =========================================================================
__global__ __launch_bounds__(256)
void offset_kernel(const float* __restrict__ q2,
                   const float* __restrict__ dw_w,
                   const float* __restrict__ dw_b,
                   const float* __restrict__ ln_g,
                   const float* __restrict__ ln_b,
                   const float* __restrict__ off_w,
                   float* __restrict__ gridbuf)
{
    const int h  = blockIdx.x;
    const int bg = blockIdx.y;
    const int b = bg / Gv, g = bg % Gv;
    const int tid = threadIdx.x;

    __shared__ float ts[GCv * Wv];
    __shared__ float ssum[Wv * 8], ssq[Wv * 8];
    __shared__ float s_mean[Wv], s_rstd[Wv];

    const float* qbase = q2 + (ll)(g * GCv) * Nv + b * Sv;

    // ---- depthwise 5x5 conv: c = tid>>1 (0..127), half xh = tid&1
    {
        const int c  = tid >> 1;
        const int xh = tid & 1;
        const int x0 = xh * 14;
        const float* wrow = dw_w + c * 25;
        const float* qc = qbase + (ll)c * Nv;

        float acc[14];
        const float bc = dw_b[c];
#pragma unroll
        for (int i = 0; i < 14; i++) acc[i] = bc;

#pragma unroll
        for (int dy = 0; dy < 5; dy++) {
            const int hh = h + dy - 2;
            if (hh < 0 || hh >= Hv) continue;
            const float* row = qc + hh * Wv;

            float r[18];
            if (xh == 0) {
                r[0] = 0.f; r[1] = 0.f;
#pragma unroll
                for (int j = 2; j < 18; j++) r[j] = row[j - 2];
            } else {
#pragma unroll
                for (int j = 0; j < 16; j++) r[j] = row[12 + j];
                r[16] = 0.f; r[17] = 0.f;
            }
#pragma unroll
            for (int dx = 0; dx < 5; dx++) {
                const float w = wrow[dy * 5 + dx];
#pragma unroll
                for (int i = 0; i < 14; i++)
                    acc[i] = fmaf(w, r[i + dx], acc[i]);
            }
        }
#pragma unroll
        for (int i = 0; i < 14; i++)
            ts[c * Wv + x0 + i] = acc[i];
    }
    __syncthreads();

    if (tid < Wv * 8) {
        const int x = tid % Wv, part = tid / Wv;
        float s = 0.f, sq = 0.f;
        for (int c = part * 16; c < part * 16 + 16; c++) {
            const float v = ts[c * Wv + x];
            s += v; sq += v * v;
        }
        ssum[x * 8 + part] = s; ssq[x * 8 + part] = sq;
    }
    __syncthreads();
    if (tid < Wv) {
        float s = 0.f, sq = 0.f;
        for (int p = 0; p < 8; p++) { s += ssum[tid * 8 + p]; sq += ssq[tid * 8 + p]; }
        const float mu  = s * (1.f / GCv);
        const float var = sq * (1.f / GCv) - mu * mu;
        s_mean[tid] = mu;
        s_rstd[tid] = rsqrtf(var + EPSv);
    }
    __syncthreads();

    for (int idx = tid; idx < GCv * Wv; idx += 256) {
        const int c = idx / Wv, x = idx % Wv;
        const float v = (ts[idx] - s_mean[x]) * s_rstd[x] * ln_g[c] + ln_b[c];
        ts[idx] = 0.5f * v * (1.f + erff(v * 0.70710678118654752f));
    }
    __syncthreads();

    if (tid < 2 * Wv) {
        const int o = tid / Wv;
        const int x = tid % Wv;
        float s = 0.f;
        const float* w = off_w + o * GCv;
        for (int c = 0; c < GCv; c++) s += w[c] * ts[c * Wv + x];
        const float off = tanhf(s) * (2.0f / 28.0f);
        const float ref = (float)(2 * (o == 0 ? h : x) + 1) * (1.0f / 28.0f) - 1.0f;
        const float pix = ((off + ref) + 1.0f) * 0.5f * 27.0f;
        gridbuf[((ll)bg * Sv + h * Wv + x) * 2 + (o == 0 ? 1 : 0)] = pix;
    }
}

// =========================================================================
// Bilinear gather -> xst hi/lo (Nv, C)
// =========================================================================
__global__ __launch_bounds__(256)
void sample_kernel(const float* __restrict__ x2,
                   const float* __restrict__ gridbuf,
                   __nv_bfloat16* __restrict__ xsth,
                   __nv_bfloat16* __restrict__ xstl)
{
    const int p = blockIdx.x;
    const int b = blockIdx.y;
    const int tid = threadIdx.x;

    __shared__ float coords[Gv][2];
    if (tid < Gv * 2) {
        const int g = tid >> 1, o = tid & 1;
        coords[g][o] = gridbuf[((ll)(b * Gv + g) * Sv + p) * 2 + o];
    }
    __syncthreads();

    const float* xb = x2 + (ll)b * Sv * Cv;
    const ll ob = ((ll)b * Sv + p) * Cv;

    for (int c = tid; c < Cv; c += 256) {
        const int g = c >> 7;
        const float px = coords[g][0], py = coords[g][1];
        const float x0f = floorf(px), y0f = floorf(py);
        const int x0 = (int)x0f, y0 = (int)y0f;
        const float wx1 = px - x0f, wy1 = py - y0f;
        const float wx0 = 1.f - wx1, wy0 = 1.f - wy1;

        float r = 0.f;
#pragma unroll
        for (int dy = 0; dy < 2; dy++) {
            const int yy = y0 + dy;
            if (yy < 0 || yy >= Hv) continue;
            const float wy = dy ? wy1 : wy0;
#pragma unroll
            for (int dx = 0; dx < 2; dx++) {
                const int xx = x0 + dx;
                if (xx < 0 || xx >= Wv) continue;
                const float wx = dx ? wx1 : wx0;
                r += wy * wx * __ldg(&xb[(ll)(yy * Wv + xx) * Cv + c]);
            }
        }
        const __nv_bfloat16 hv = __float2bfloat16(r);
        xsth[ob + c] = hv;
        xstl[ob + c] = __float2bfloat16(r - __bfloat162float(hv));
    }
}

// =========================================================================
extern "C" void kernel_launch(void* const* d_in, const int* in_sizes, int n_in,
                              void* d_out, int out_size)
{
    (void)in_sizes; (void)n_in; (void)out_size;

    const float* x1   = (const float*)d_in[0];
    const float* x2   = (const float*)d_in[1];
    const float* dw_w = (const float*)d_in[2];
    const float* dw_b = (const float*)d_in[3];
    const float* ln_g = (const float*)d_in[4];
    const float* ln_b = (const float*)d_in[5];
    const float* offw = (const float*)d_in[6];
    const float* wq   = (const float*)d_in[7];
    const float* bq   = (const float*)d_in[8];
    const float* wk   = (const float*)d_in[9];
    const float* bk   = (const float*)d_in[10];
    const float* wv   = (const float*)d_in[11];
    const float* bv   = (const float*)d_in[12];
    const float* wo   = (const float*)d_in[13];
    const float* bo   = (const float*)d_in[14];

    float* out  = (float*)d_out;
    float* attn = out + (ll)Bv * Sv * Cv;

    cudaFuncSetAttribute(mma_gemm, cudaFuncAttributeMaxDynamicSharedMemorySize, MMA_SMEM);
    cudaFuncSetAttribute(logits_mma, cudaFuncAttributeMaxDynamicSharedMemorySize, LSMEM);

    void *p;
#define SYM(name, var) cudaGetSymbolAddress(&p, name); float* var = (float*)p;
#define SYMB(name, var) cudaGetSymbolAddress(&p, name); __nv_bfloat16* var = (__nv_bfloat16*)p;
    SYM(g_q2, pq2)  SYM(g_grid, pgrid)  SYM(g_rsum, prsum)
    SYMB(g_qh, qhp) SYMB(g_ql, qlp)
    SYMB(g_kh, khp) SYMB(g_kl, klp)
    SYMB(g_vh, vhp) SYMB(g_vl, vlp)
    SYMB(g_x1h, x1h)  SYMB(g_x1l, x1l)
    SYMB(g_xsth, xsth) SYMB(g_xstl, xstl)
    SYMB(g_avth, avth) SYMB(g_avtl, avtl)
    SYMB(g_wqh, wqh) SYMB(g_wql, wql)
    SYMB(g_wkh, wkh) SYMB(g_wkl, wkl)
    SYMB(g_wvh, wvh) SYMB(g_wvl, wvl)
    SYMB(g_woh, woh) SYMB(g_wol, wol)
#undef SYM
#undef SYMB

    const int NW = Cv * Cv;
    const int NX = Nv * Cv;
    const dim3 thr(256);

    // ---- splits (weights in one launch) + x1
    split4_bf16<<<dim3((NW + 255) / 256, 4), thr>>>(
        wq, wk, wv, wo, wqh, wql, wkh, wkl, wvh, wvl, woh, wol, NW);
    split_bf16<<<(NX + 255) / 256, thr>>>(x1, x1h, x1l, NX);

    // ---- q = wq @ x1^T : (C, Nv) fp32 + hi/lo
    mma_gemm<<<dim3(Nv / 128, Cv / 128, 1), thr, MMA_SMEM>>>(
        wqh, wql, wqh, wql, x1h, x1l, pq2, qhp, qlp, qhp, qlp,
        Cv, Nv, bq, bq, nullptr);

    // ---- offsets + sampling (hi/lo out)
    offset_kernel<<<dim3(Hv, Bv * Gv), thr>>>(pq2, dw_w, dw_b, ln_g, ln_b, offw, pgrid);
    sample_kernel<<<dim3(Sv, Bv), thr>>>(x2, pgrid, xsth, xstl);

    // ---- k and v in ONE launch (z selects)
    mma_gemm<<<dim3(Nv / 128, Cv / 128, 2), thr, MMA_SMEM>>>(
        wkh, wkl, wvh, wvl, xsth, xstl, nullptr, khp, klp, vhp, vlp,
        Cv, Nv, bk, bv, nullptr);

    // ---- logits: exp(QK^T * scale) -> attn + per-CTA row sums
    logits_mma<<<dim3(7, Bv * NHv), thr, LSMEM>>>(qhp, qlp, khp, klp, attn, prsum);

    // ---- AV + normalize (pipelined): attn /= rsum (written back), avt = P.V
    av_mma<<<dim3(7, Bv * NHv), thr>>>(attn, prsum, vhp, vlp, avth, avtl);

    // ---- out = avt @ wo^T + bo -> d_out (Nv, C)
    mma_gemm<<<dim3(Cv / 128, Nv / 128, 1), thr, MMA_SMEM>>>(
        avth, avtl, avth, avtl, woh, wol, out, nullptr, nullptr, nullptr, nullptr,
        Cv, Cv, nullptr, nullptr, bo);
}

// round 10
// speedup vs baseline: 1.0739x; 1.0739x over previous
#include <cuda_runtime.h>
#include <cuda_bf16.h>
#include <math.h>
#include <stdint.h>

#define Bv   8
#define Cv   768
#define Hv   28
#define Wv   28
#define Gv   6
#define GCv  128
#define NHv  12
#define HCv  64
#define Sv   784
#define Nv   (Bv * Sv)      // 6272
#define SCALEv 0.125f
#define EPSv 1e-5f
#define PADE 4096

typedef long long ll;

// ---------------- scratch (device globals; no allocation) ----------------
__device__ float g_q2 [Cv * Nv];                       // (768, 6272) fp32 (offset path)
__device__ float g_grid[Bv * Gv * Sv * 2];
__device__ float g_rsum[Bv * NHv * Sv];                // softmax row sums

__device__ __nv_bfloat16 g_qh [Cv * Nv + PADE], g_ql [Cv * Nv + PADE];   // (C, Nv)
__device__ __nv_bfloat16 g_kh [Cv * Nv + PADE], g_kl [Cv * Nv + PADE];
__device__ __nv_bfloat16 g_vh [Cv * Nv + PADE], g_vl [Cv * Nv + PADE];
__device__ __nv_bfloat16 g_x1h [Nv * Cv], g_x1l [Nv * Cv];               // (Nv, C)
__device__ __nv_bfloat16 g_xsth[Nv * Cv], g_xstl[Nv * Cv];
__device__ __nv_bfloat16 g_avth[Nv * Cv], g_avtl[Nv * Cv];
__device__ __nv_bfloat16 g_wqh [Cv * Cv], g_wql [Cv * Cv];
__device__ __nv_bfloat16 g_wkh [Cv * Cv], g_wkl [Cv * Cv];
__device__ __nv_bfloat16 g_wvh [Cv * Cv], g_wvl [Cv * Cv];
__device__ __nv_bfloat16 g_woh [Cv * Cv], g_wol [Cv * Cv];

// ======================= PTX helpers (sm_80-portable) =====================
__device__ __forceinline__ uint32_t smem_u32(const void* p) {
    uint32_t a;
    asm("{ .reg .u64 t; cvta.to.shared.u64 t, %1; cvt.u32.u64 %0, t; }" : "=r"(a) : "l"(p));
    return a;
}
__device__ __forceinline__ void cpa16(uint32_t dst, const void* src) {
    asm volatile("cp.async.cg.shared.global [%0], [%1], 16;" :: "r"(dst), "l"(src));
}
#define CP_COMMIT() asm volatile("cp.async.commit_group;" ::: "memory")
#define CP_WAIT1()  asm volatile("cp.async.wait_group 1;" ::: "memory")
#define CP_WAIT0()  asm volatile("cp.async.wait_group 0;" ::: "memory")

__device__ __forceinline__ void ldsm4(uint32_t* r, uint32_t addr) {
    asm volatile("ldmatrix.sync.aligned.m8n8.x4.shared.b16 {%0,%1,%2,%3}, [%4];"
        : "=r"(r[0]), "=r"(r[1]), "=r"(r[2]), "=r"(r[3]) : "r"(addr));
}
__device__ __forceinline__ void ldsm4t(uint32_t* r, uint32_t addr) {
    asm volatile("ldmatrix.sync.aligned.m8n8.x4.trans.shared.b16 {%0,%1,%2,%3}, [%4];"
        : "=r"(r[0]), "=r"(r[1]), "=r"(r[2]), "=r"(r[3]) : "r"(addr));
}
__device__ __forceinline__ void mma16816(float* c, const uint32_t* a, const uint32_t* b) {
    asm volatile(
        "mma.sync.aligned.m16n8k16.row.col.f32.bf16.bf16.f32 "
        "{%0,%1,%2,%3}, {%4,%5,%6,%7}, {%8,%9}, {%0,%1,%2,%3};"
        : "+f"(c[0]), "+f"(c[1]), "+f"(c[2]), "+f"(c[3])
        : "r"(a[0]), "r"(a[1]), "r"(a[2]), "r"(a[3]), "r"(b[0]), "r"(b[1]));
}
__device__ __forceinline__ void store_hilo(__nv_bfloat16* Hp, __nv_bfloat16* Lp,
                                           ll idx, float a, float b) {
    const __nv_bfloat16 ha = __float2bfloat16(a), hb = __float2bfloat16(b);
    __nv_bfloat162 hv; hv.x = ha; hv.y = hb;
    *(__nv_bfloat162*)(Hp + idx) = hv;
    __nv_bfloat162 lv;
    lv.x = __float2bfloat16(a - __bfloat162float(ha));
    lv.y = __float2bfloat16(b - __bfloat162float(hb));
    *(__nv_bfloat162*)(Lp + idx) = lv;
}

// =========================================================================
// bf16x3 warp-MMA GEMM (dual-set via blockIdx.z):
//   C[M x N] = A(MxK) . B(NxK)^T (+bias_m +bias_n)
// =========================================================================
#define KC       32
#define TPAD     40
#define TILE_B   (128 * TPAD * 2)
#define STAGE_B  (4 * TILE_B)
#define MMA_SMEM (2 * STAGE_B)

__global__ void __launch_bounds__(256, 2)
mma_gemm(const __nv_bfloat16* __restrict__ Ah, const __nv_bfloat16* __restrict__ Al,
         const __nv_bfloat16* __restrict__ Ah2, const __nv_bfloat16* __restrict__ Al2,
         const __nv_bfloat16* __restrict__ Bh, const __nv_bfloat16* __restrict__ Bl,
         float* __restrict__ Cf,
         __nv_bfloat16* __restrict__ Chi, __nv_bfloat16* __restrict__ Clo,
         __nv_bfloat16* __restrict__ Chi2, __nv_bfloat16* __restrict__ Clo2,
         int K, int ldc,
         const float* __restrict__ bias_m, const float* __restrict__ bias_m2,
         const float* __restrict__ bias_n)
{
    if (blockIdx.z == 1) {
        Ah = Ah2; Al = Al2; Chi = Chi2; Clo = Clo2; bias_m = bias_m2; Cf = nullptr;
    }
    extern __shared__ char smem[];
    const uint32_t sb = smem_u32(smem);
    const int tid = threadIdx.x;
    const int wid = tid >> 5, lane = tid & 31;

    const int m0 = blockIdx.y * 128;
    const int n0 = blockIdx.x * 128;

    const __nv_bfloat16* srcs[4] = {
        Ah + (ll)m0 * K, Al + (ll)m0 * K,
        Bh + (ll)n0 * K, Bl + (ll)n0 * K };

    const int NCk = K / KC;

    float acc[2][8][4];
#pragma unroll
    for (int i = 0; i < 2; i++)
#pragma unroll
        for (int j = 0; j < 8; j++)
#pragma unroll
            for (int r = 0; r < 4; r++) acc[i][j][r] = 0.f;

    auto issue = [&](int c) {
        const uint32_t st = sb + (uint32_t)(c & 1) * STAGE_B;
        const ll kb = (ll)c * KC;
#pragma unroll
        for (int t = 0; t < 4; t++) {
            const __nv_bfloat16* src = srcs[t];
            const uint32_t tb = st + t * TILE_B;
#pragma unroll
            for (int it = 0; it < 2; it++) {
                const int idx = tid + it * 256;
                const int row = idx >> 2;
                const int q   = idx & 3;
                cpa16(tb + row * 80 + q * 16, src + (ll)row * K + kb + q * 8);
            }
        }
    };

    issue(0); CP_COMMIT();

    const int wm = (wid & 3) * 32;
    const int wn = (wid >> 2) * 64;
    const int rsel = lane & 7;
    const int aRow = wm + rsel + ((lane >> 3) & 1) * 8;
    const int aColB = ((lane >> 4) & 1) * 16;
    const int bRow = wn + rsel + ((lane >> 4) & 1) * 8;
    const int bColB = ((lane >> 3) & 1) * 16;

    for (int c = 0; c < NCk; c++) {
        if (c + 1 < NCk) issue(c + 1);
        CP_COMMIT();
        CP_WAIT1();
        __syncthreads();

        const uint32_t st = sb + (uint32_t)(c & 1) * STAGE_B;
#pragma unroll
        for (int kst = 0; kst < 2; kst++) {
            uint32_t ah[2][4], al[2][4];
#pragma unroll
            for (int mf = 0; mf < 2; mf++) {
                const uint32_t ra = st + (aRow + mf * 16) * 80 + kst * 32 + aColB;
                ldsm4(ah[mf], ra);
                ldsm4(al[mf], ra + TILE_B);
            }
            uint32_t bh[8][2], bl[8][2];
#pragma unroll
            for (int nf2 = 0; nf2 < 4; nf2++) {
                const uint32_t rb = st + 2 * TILE_B + (bRow + nf2 * 16) * 80 + kst * 32 + bColB;
                uint32_t t4[4];
                ldsm4(t4, rb);
                bh[nf2 * 2][0] = t4[0]; bh[nf2 * 2][1] = t4[1];
                bh[nf2 * 2 + 1][0] = t4[2]; bh[nf2 * 2 + 1][1] = t4[3];
                ldsm4(t4, rb + TILE_B);
                bl[nf2 * 2][0] = t4[0]; bl[nf2 * 2][1] = t4[1];
                bl[nf2 * 2 + 1][0] = t4[2]; bl[nf2 * 2 + 1][1] = t4[3];
            }
#pragma unroll
            for (int mf = 0; mf < 2; mf++)
#pragma unroll
                for (int nf = 0; nf < 8; nf++) {
                    mma16816(acc[mf][nf], ah[mf], bh[nf]);
                    mma16816(acc[mf][nf], ah[mf], bl[nf]);
                    mma16816(acc[mf][nf], al[mf], bh[nf]);
                }
        }
        __syncthreads();
    }

#pragma unroll
    for (int mf = 0; mf < 2; mf++) {
        const int r0 = m0 + wm + mf * 16 + (lane >> 2);
        const int r1 = r0 + 8;
        const float bm0 = bias_m ? __ldg(&bias_m[r0]) : 0.f;
        const float bm1 = bias_m ? __ldg(&bias_m[r1]) : 0.f;
#pragma unroll
        for (int nf = 0; nf < 8; nf++) {
            const int col = n0 + wn + nf * 8 + (lane & 3) * 2;
            float bn0 = 0.f, bn1 = 0.f;
            if (bias_n) { bn0 = __ldg(&bias_n[col]); bn1 = __ldg(&bias_n[col + 1]); }
            const float* a = acc[mf][nf];
            const float v00 = a[0] + bm0 + bn0, v01 = a[1] + bm0 + bn1;
            const float v10 = a[2] + bm1 + bn0, v11 = a[3] + bm1 + bn1;
            const ll i0 = (ll)r0 * ldc + col;
            const ll i1 = (ll)r1 * ldc + col;
            if (Cf) {
                float2 f0; f0.x = v00; f0.y = v01; *(float2*)&Cf[i0] = f0;
                float2 f1; f1.x = v10; f1.y = v11; *(float2*)&Cf[i1] = f1;
            }
            if (Chi) {
                store_hilo(Chi, Clo, i0, v00, v01);
                store_hilo(Chi, Clo, i1, v10, v11);
            }
        }
    }
}

// =========================================================================
// fp32 -> bf16 hi/lo split (single) and 4-way weight split
// =========================================================================
__global__ __launch_bounds__(256)
void split_bf16(const float* __restrict__ in, __nv_bfloat16* __restrict__ hi,
                __nv_bfloat16* __restrict__ lo, int n)
{
    const int i = blockIdx.x * 256 + threadIdx.x;
    if (i < n) {
        const float x = in[i];
        const __nv_bfloat16 h = __float2bfloat16(x);
        hi[i] = h;
        lo[i] = __float2bfloat16(x - __bfloat162float(h));
    }
}

__global__ __launch_bounds__(256)
void split4_bf16(const float* __restrict__ w0, const float* __restrict__ w1,
                 const float* __restrict__ w2, const float* __restrict__ w3,
                 __nv_bfloat16* __restrict__ h0, __nv_bfloat16* __restrict__ l0,
                 __nv_bfloat16* __restrict__ h1, __nv_bfloat16* __restrict__ l1,
                 __nv_bfloat16* __restrict__ h2, __nv_bfloat16* __restrict__ l2,
                 __nv_bfloat16* __restrict__ h3, __nv_bfloat16* __restrict__ l3,
                 int n)
{
    const int i = blockIdx.x * 256 + threadIdx.x;
    if (i >= n) return;
    const int s = blockIdx.y;
    const float* in = (s == 0) ? w0 : (s == 1) ? w1 : (s == 2) ? w2 : w3;
    __nv_bfloat16* hi = (s == 0) ? h0 : (s == 1) ? h1 : (s == 2) ? h2 : h3;
    __nv_bfloat16* lo = (s == 0) ? l0 : (s == 1) ? l1 : (s == 2) ? l2 : l3;
    const float x = in[i];
    const __nv_bfloat16 h = __float2bfloat16(x);
    hi[i] = h;
    lo[i] = __float2bfloat16(x - __bfloat162float(h));
}

// =========================================================================
// Logits (Q-resident, K-streamed): one CTA per (bh, 128-row i-tile).
// =========================================================================
#define LROWB 272
#define LT    17408
#define LSK   (2 * LT)
#define LSMEM (6 * LT)

__global__ void __launch_bounds__(256, 1)
logits_mma(const __nv_bfloat16* __restrict__ qh, const __nv_bfloat16* __restrict__ ql,
           const __nv_bfloat16* __restrict__ kh, const __nv_bfloat16* __restrict__ kl,
           float* __restrict__ attn, float* __restrict__ rsum)
{
    extern __shared__ char smem[];
    __shared__ float srow[128];
    const uint32_t sb = smem_u32(smem);
    const int tid = threadIdx.x;
    const int wid = tid >> 5, lane = tid & 31;
    const int bh = blockIdx.y, b = bh / NHv, h = bh % NHv;
    const int i0 = blockIdx.x * 128;

    if (tid < 128) srow[tid] = 0.f;

    const ll off = (ll)(h * HCv) * Nv + (ll)b * Sv;
    const __nv_bfloat16* q0 = qh + off + i0;
    const __nv_bfloat16* q1 = ql + off + i0;
    const __nv_bfloat16* k0 = kh + off;
    const __nv_bfloat16* k1 = kl + off;

#pragma unroll
    for (int it = 0; it < 4; it++) {
        const int idx = tid + it * 256;
        const int row = idx >> 4, q = idx & 15;
        cpa16(sb + row * LROWB + q * 16, q0 + (ll)row * Nv + q * 8);
        cpa16(sb + LT + row * LROWB + q * 16, q1 + (ll)row * Nv + q * 8);
    }
    CP_COMMIT();

    auto issueK = [&](int jc) {
        const uint32_t st = sb + LSK + (uint32_t)(jc & 1) * (2 * LT);
        const ll jb = (ll)jc * 128;
#pragma unroll
        for (int it = 0; it < 4; it++) {
            const int idx = tid + it * 256;
            const int row = idx >> 4, q = idx & 15;
            const ll go = (ll)row * Nv + jb + q * 8;
            cpa16(st + row * LROWB + q * 16, k0 + go);
            cpa16(st + LT + row * LROWB + q * 16, k1 + go);
        }
    };
    issueK(0); CP_COMMIT();

    const int wm = (wid & 3) * 32;
    const int wn = (wid >> 2) * 64;
    const int arowk = (lane & 7) + ((lane >> 4) & 1) * 8;
    const int acolm = wm + ((lane >> 3) & 1) * 8;
    const int browk = (lane & 7) + ((lane >> 3) & 1) * 8;
    const int bcoln = wn + ((lane >> 4) & 1) * 8;
    const int cb2 = (lane & 3) * 2;

    float* Cp = attn + (ll)bh * Sv * Sv;
    float rs[2][2] = {{0.f, 0.f}, {0.f, 0.f}};

    for (int jc = 0; jc < 7; jc++) {
        if (jc + 1 < 7) { issueK(jc + 1); CP_COMMIT(); CP_WAIT1(); }
        else           { CP_WAIT0(); }
        __syncthreads();

        const uint32_t sKh = sb + LSK + (uint32_t)(jc & 1) * (2 * LT);

        float acc[2][8][4];
#pragma unroll
        for (int i = 0; i < 2; i++)
#pragma unroll
            for (int j = 0; j < 8; j++)
#pragma unroll
                for (int r = 0; r < 4; r++) acc[i][j][r] = 0.f;

#pragma unroll
        for (int kst = 0; kst < 4; kst++) {
            uint32_t ah[2][4], al[2][4];
#pragma unroll
            for (int mf = 0; mf < 2; mf++) {
                const uint32_t ra = sb + (kst * 16 + arowk) * LROWB + (acolm + mf * 16) * 2;
                ldsm4t(ah[mf], ra);
                ldsm4t(al[mf], ra + LT);
            }
            uint32_t bhf[8][2], blf[8][2];
#pragma unroll
            for (int nf2 = 0; nf2 < 4; nf2++) {
                const uint32_t rb = sKh + (kst * 16 + browk) * LROWB + (bcoln + nf2 * 16) * 2;
                uint32_t t4[4];
                ldsm4t(t4, rb);
                bhf[nf2 * 2][0] = t4[0]; bhf[nf2 * 2][1] = t4[1];
                bhf[nf2 * 2 + 1][0] = t4[2]; bhf[nf2 * 2 + 1][1] = t4[3];
                ldsm4t(t4, rb + LT);
                blf[nf2 * 2][0] = t4[0]; blf[nf2 * 2][1] = t4[1];
                blf[nf2 * 2 + 1][0] = t4[2]; blf[nf2 * 2 + 1][1] = t4[3];
            }
#pragma unroll
            for (int mf = 0; mf < 2; mf++)
#pragma unroll
                for (int nf = 0; nf < 8; nf++) {
                    mma16816(acc[mf][nf], ah[mf], bhf[nf]);
                    mma16816(acc[mf][nf], ah[mf], blf[nf]);
                    mma16816(acc[mf][nf], al[mf], bhf[nf]);
                }
        }

        const int j0 = jc * 128;
#pragma unroll
        for (int mf = 0; mf < 2; mf++) {
            const int r0 = i0 + wm + mf * 16 + (lane >> 2);
            const int r1 = r0 + 8;
#pragma unroll
            for (int nf = 0; nf < 8; nf++) {
                const int col = j0 + wn + nf * 8 + cb2;
                if (col >= Sv) continue;
                const float* a = acc[mf][nf];
                if (r0 < Sv) {
                    float2 f;
                    f.x = __expf(a[0] * SCALEv);
                    f.y = __expf(a[1] * SCALEv);
                    *(float2*)&Cp[(ll)r0 * Sv + col] = f;
                    rs[mf][0] += f.x + f.y;
                }
                if (r1 < Sv) {
                    float2 f;
                    f.x = __expf(a[2] * SCALEv);
                    f.y = __expf(a[3] * SCALEv);
                    *(float2*)&Cp[(ll)r1 * Sv + col] = f;
                    rs[mf][1] += f.x + f.y;
                }
            }
        }
        __syncthreads();
    }

#pragma unroll
    for (int mf = 0; mf < 2; mf++) {
        float s0 = rs[mf][0], s1 = rs[mf][1];
        s0 += __shfl_xor_sync(0xffffffffu, s0, 1);
        s0 += __shfl_xor_sync(0xffffffffu, s0, 2);
        s1 += __shfl_xor_sync(0xffffffffu, s1, 1);
        s1 += __shfl_xor_sync(0xffffffffu, s1, 2);
        if ((lane & 3) == 0) {
            const int lr = wm + mf * 16 + (lane >> 2);
            atomicAdd(&srow[lr], s0);
            atomicAdd(&srow[lr + 8], s1);
        }
    }
    __syncthreads();
    if (tid < 128 && i0 + tid < Sv)
        rsum[(ll)bh * Sv + i0 + tid] = srow[tid];
}

// =========================================================================
// AV + softmax-normalize (pipelined)
// =========================================================================
#define AVROWB 80
#define AV_A_H   0
#define AV_A_L   10240
#define AV_B     20480
#define AV_SMEMB (20480 + 2 * 10240)

__global__ void __launch_bounds__(256, 1)
av_mma(float* __restrict__ attn, const float* __restrict__ rsum,
       const __nv_bfloat16* __restrict__ vh, const __nv_bfloat16* __restrict__ vl,
       __nv_bfloat16* __restrict__ avth, __nv_bfloat16* __restrict__ avtl)
{
    __shared__ char smc[AV_SMEMB];
    __shared__ float sm_inv[128];
    const uint32_t sb = smem_u32(smc);

    const int tid = threadIdx.x;
    const int wid = tid >> 5, lane = tid & 31;
    const int bh = blockIdx.y, b = bh / NHv, h = bh % NHv;
    const int n0 = blockIdx.x * 128;

    float* Ap = attn + (ll)bh * Sv * Sv;
    const __nv_bfloat16* vbh = vh + (ll)(h * HCv) * Nv + (ll)b * Sv;
    const __nv_bfloat16* vbl = vl + (ll)(h * HCv) * Nv + (ll)b * Sv;

    if (tid < 128) {
        const int gn = n0 + tid;
        sm_inv[tid] = (gn < Sv) ? (1.f / rsum[(ll)bh * Sv + gn]) : 0.f;
    }
    __syncthreads();

    float acc[2][4][4];
#pragma unroll
    for (int i = 0; i < 2; i++)
#pragma unroll
        for (int j = 0; j < 4; j++)
#pragma unroll
            for (int r = 0; r < 4; r++) acc[i][j][r] = 0.f;

    const int wm = (wid & 3) * 32;
    const int wn = (wid >> 2) * 32;
    const int rsel = lane & 7;
    const int aRow = wm + rsel + ((lane >> 3) & 1) * 8;
    const int aColB = ((lane >> 4) & 1) * 16;
    const int bRow = wn + rsel + ((lane >> 4) & 1) * 8;
    const int bColB = ((lane >> 3) & 1) * 16;

    const int vrow = tid >> 2;
    const int vq   = tid & 3;

    float4 areg[4];

    auto issueB = [&](int kc) {
        const int kb = kc * 32;
        const uint32_t bb = sb + AV_B + (uint32_t)(kc & 1) * 10240;
        cpa16(bb + vrow * AVROWB + vq * 16, vbh + (ll)vrow * Nv + kb + vq * 8);
        cpa16(bb + 5120 + vrow * AVROWB + vq * 16, vbl + (ll)vrow * Nv + kb + vq * 8);
    };
    auto loadA = [&](int kc) {
        const int kb = kc * 32;
#pragma unroll
        for (int it = 0; it < 4; it++) {
            const int idx4 = tid + it * 256;
            const int row = idx4 >> 3;
            const int qq  = idx4 & 7;
            const int gn = n0 + row;
            const int gk = kb + qq * 4;
            areg[it] = make_float4(0.f, 0.f, 0.f, 0.f);
            if (gn < Sv && gk < Sv)
                areg[it] = *(const float4*)&Ap[(ll)gn * Sv + gk];
        }
    };

    issueB(0); CP_COMMIT();
    loadA(0);

    for (int kc = 0; kc < 25; kc++) {
        const int kb = kc * 32;
#pragma unroll
        for (int it = 0; it < 4; it++) {
            const int idx4 = tid + it * 256;
            const int row = idx4 >> 3;
            const int qq  = idx4 & 7;
            const int gn = n0 + row;
            const int gk = kb + qq * 4;
            float4 v = areg[it];
            const float inv = sm_inv[row];
            v.x *= inv; v.y *= inv; v.z *= inv; v.w *= inv;
            if (gn < Sv && gk < Sv) *(float4*)&Ap[(ll)gn * Sv + gk] = v;
            const __nv_bfloat16 h0 = __float2bfloat16(v.x), h1 = __float2bfloat16(v.y);
            const __nv_bfloat16 h2 = __float2bfloat16(v.z), h3 = __float2bfloat16(v.w);
            __nv_bfloat162 p01, p23, q01, q23;
            p01.x = h0; p01.y = h1; p23.x = h2; p23.y = h3;
            q01.x = __float2bfloat16(v.x - __bfloat162float(h0));
            q01.y = __float2bfloat16(v.y - __bfloat162float(h1));
            q23.x = __float2bfloat16(v.z - __bfloat162float(h2));
            q23.y = __float2bfloat16(v.w - __bfloat162float(h3));
            uint2 hw, lw;
            hw.x = *(uint32_t*)&p01; hw.y = *(uint32_t*)&p23;
            lw.x = *(uint32_t*)&q01; lw.y = *(uint32_t*)&q23;
            *(uint2*)(smc + AV_A_H + row * AVROWB + qq * 8) = hw;
            *(uint2*)(smc + AV_A_L + row * AVROWB + qq * 8) = lw;
        }
        if (kc + 1 < 25) {
            issueB(kc + 1); CP_COMMIT();
            loadA(kc + 1);
            CP_WAIT1();
        } else {
            CP_WAIT0();
        }
        __syncthreads();

        const uint32_t sBh = sb + AV_B + (uint32_t)(kc & 1) * 10240;
        const uint32_t sAh = sb + AV_A_H;
#pragma unroll
        for (int kst = 0; kst < 2; kst++) {
            uint32_t ah[2][4], al[2][4];
#pragma unroll
            for (int mf = 0; mf < 2; mf++) {
                const uint32_t ra = sAh + (aRow + mf * 16) * AVROWB + kst * 32 + aColB;
                ldsm4(ah[mf], ra);
                ldsm4(al[mf], ra + (AV_A_L - AV_A_H));
            }
            uint32_t bhf[4][2], blf[4][2];
#pragma unroll
            for (int nf2 = 0; nf2 < 2; nf2++) {
                const uint32_t rb = sBh + (bRow + nf2 * 16) * AVROWB + kst * 32 + bColB;
                uint32_t t4[4];
                ldsm4(t4, rb);
                bhf[nf2 * 2][0] = t4[0]; bhf[nf2 * 2][1] = t4[1];
                bhf[nf2 * 2 + 1][0] = t4[2]; bhf[nf2 * 2 + 1][1] = t4[3];
                ldsm4(t4, rb + 5120);
                blf[nf2 * 2][0] = t4[0]; blf[nf2 * 2][1] = t4[1];
                blf[nf2 * 2 + 1][0] = t4[2]; blf[nf2 * 2 + 1][1] = t4[3];
            }
#pragma unroll
            for (int mf = 0; mf < 2; mf++)
#pragma unroll
                for (int nf = 0; nf < 4; nf++) {
                    mma16816(acc[mf][nf], ah[mf], bhf[nf]);
                    mma16816(acc[mf][nf], ah[mf], blf[nf]);
                    mma16816(acc[mf][nf], al[mf], bhf[nf]);
                }
        }
        __syncthreads();
    }

#pragma unroll
    for (int mf = 0; mf < 2; mf++) {
        const int r0 = n0 + wm + mf * 16 + (lane >> 2);
        const int r1 = r0 + 8;
#pragma unroll
        for (int nf = 0; nf < 4; nf++) {
            const int cold = wn + nf * 8 + (lane & 3) * 2;
            const ll colg = (ll)h * HCv + cold;
            const float* a = acc[mf][nf];
            if (r0 < Sv)
                store_hilo(avth, avtl, ((ll)b * Sv + r0) * Cv + colg, a[0], a[1]);
            if (r1 < Sv)
                store_hilo(avth, avtl, ((ll)b * Sv + r1) * Cv + colg, a[2], a[3]);
        }
    }
}

// =========================================================================
// Fused dwconv5x5 -> LN -> GELU -> offset proj -> sampling coords
// Conv inputs staged in smem (coalesced float4 LDG), register sliding window.
// =========================================================================
#define OFF_QS   (5 * GCv * Wv)              // 17920 floats
#define OFF_SMEM ((OFF_QS + GCv * Wv) * 4)   // + ts 128*28 -> 86016 B

__global__ void __launch_bounds__(256)
offset_kernel(const float* __restrict__ q2,
              const float* __restrict__ dw_w,
              const float* __restrict__ dw_b,
              const float* __restrict__ ln_g,
              const float* __restrict__ ln_b,
              const float* __restrict__ off_w,
              float* __restrict__ gridbuf)
{
    extern __shared__ float dsm[];
    float* qs = dsm;                 // [5][128][28]
    float* ts = dsm + OFF_QS;        // [128][28]
    __shared__ float ssum[Wv * 8], ssq[Wv * 8];
    __shared__ float s_mean[Wv], s_rstd[Wv];

    const int h  = blockIdx.x;
    const int bg = blockIdx.y;
    const int b = bg / Gv, g = bg % Gv;
    const int tid = threadIdx.x;

    const float* qbase = q2 + (ll)(g * GCv) * Nv + b * Sv;

    // ---- stage 5 padded rows x 128 channels, coalesced float4
    for (int idx = tid; idx < 5 * GCv * 7; idx += 256) {
        const int xq = idx % 7;
        const int t  = idx / 7;
        const int c  = t & 127;
        const int r  = t >> 7;
        const int hh = h + r - 2;
        float4 v = make_float4(0.f, 0.f, 0.f, 0.f);
        if (hh >= 0 && hh < Hv)
            v = *(const float4*)&qbase[(ll)c * Nv + hh * Wv + xq * 4];
        *(float4*)&qs[(r * GCv + c) * Wv + xq * 4] = v;
    }
    __syncthreads();

    // ---- conv from smem, register sliding window
    {
        const int c  = tid >> 1;
        const int xh = tid & 1;
        const int x0 = xh * 14;
        const float* wrow = dw_w + c * 25;

        float acc[14];
        const float bc = dw_b[c];
#pragma unroll
        for (int i = 0; i < 14; i++) acc[i] = bc;

#pragma unroll
        for (int dy = 0; dy < 5; dy++) {
            const float* row = &qs[(dy * GCv + c) * Wv];
            float r[18];
            if (xh == 0) {
                r[0] = 0.f; r[1] = 0.f;
#pragma unroll
                for (int j = 2; j < 18; j++) r[j] = row[j - 2];
            } else {
#pragma unroll
                for (int j = 0; j < 16; j++) r[j] = row[12 + j];
                r[16] = 0.f; r[17] = 0.f;
            }
#pragma unroll
            for (int dx = 0; dx < 5; dx++) {
                const float w = wrow[dy * 5 + dx];
#pragma unroll
                for (int i = 0; i < 14; i++)
                    acc[i] = fmaf(w, r[i + dx], acc[i]);
            }
        }
#pragma unroll
        for (int i = 0; i < 14; i++)
            ts[c * Wv + x0 + i] = acc[i];
    }
    __syncthreads();

    if (tid < Wv * 8) {
        const int x = tid % Wv, part = tid / Wv;
        float s = 0.f, sq = 0.f;
        for (int c = part * 16; c < part * 16 + 16; c++) {
            const float v = ts[c * Wv + x];
            s += v; sq += v * v;
        }
        ssum[x * 8 + part] = s; ssq[x * 8 + part] = sq;
    }
    __syncthreads();
    if (tid < Wv) {
        float s = 0.f, sq = 0.f;
        for (int p = 0; p < 8; p++) { s += ssum[tid * 8 + p]; sq += ssq[tid * 8 + p]; }
        const float mu  = s * (1.f / GCv);
        const float var = sq * (1.f / GCv) - mu * mu;
        s_mean[tid] = mu;
        s_rstd[tid] = rsqrtf(var + EPSv);
    }
    __syncthreads();

    for (int idx = tid; idx < GCv * Wv; idx += 256) {
        const int c = idx / Wv, x = idx % Wv;
        const float v = (ts[idx] - s_mean[x]) * s_rstd[x] * ln_g[c] + ln_b[c];
        ts[idx] = 0.5f * v * (1.f + erff(v * 0.70710678118654752f));
    }
    __syncthreads();

    if (tid < 2 * Wv) {
        const int o = tid / Wv;
        const int x = tid % Wv;
        float s = 0.f;
        const float* w = off_w + o * GCv;
        for (int c = 0; c < GCv; c++) s += w[c] * ts[c * Wv + x];
        const float off = tanhf(s) * (2.0f / 28.0f);
        const float ref = (float)(2 * (o == 0 ? h : x) + 1) * (1.0f / 28.0f) - 1.0f;
        const float pix = ((off + ref) + 1.0f) * 0.5f * 27.0f;
        gridbuf[((ll)bg * Sv + h * Wv + x) * 2 + (o == 0 ? 1 : 0)] = pix;
    }
}

// =========================================================================
// Bilinear gather -> xst hi/lo (Nv, C)
// =========================================================================
__global__ __launch_bounds__(256)
void sample_kernel(const float* __restrict__ x2,
                   const float* __restrict__ gridbuf,
                   __nv_bfloat16* __restrict__ xsth,
                   __nv_bfloat16* __restrict__ xstl)
{
    const int p = blockIdx.x;
    const int b = blockIdx.y;
    const int tid = threadIdx.x;

    __shared__ float coords[Gv][2];
    if (tid < Gv * 2) {
        const int g = tid >> 1, o = tid & 1;
        coords[g][o] = gridbuf[((ll)(b * Gv + g) * Sv + p) * 2 + o];
    }
    __syncthreads();

    const float* xb = x2 + (ll)b * Sv * Cv;
    const ll ob = ((ll)b * Sv + p) * Cv;

    for (int c = tid; c < Cv; c += 256) {
        const int g = c >> 7;
        const float px = coords[g][0], py = coords[g][1];
        const float x0f = floorf(px), y0f = floorf(py);
        const int x0 = (int)x0f, y0 = (int)y0f;
        const float wx1 = px - x0f, wy1 = py - y0f;
        const float wx0 = 1.f - wx1, wy0 = 1.f - wy1;

        float r = 0.f;
#pragma unroll
        for (int dy = 0; dy < 2; dy++) {
            const int yy = y0 + dy;
            if (yy < 0 || yy >= Hv) continue;
            const float wy = dy ? wy1 : wy0;
#pragma unroll
            for (int dx = 0; dx < 2; dx++) {
                const int xx = x0 + dx;
                if (xx < 0 || xx >= Wv) continue;
                const float wx = dx ? wx1 : wx0;
                r += wy * wx * __ldg(&xb[(ll)(yy * Wv + xx) * Cv + c]);
            }
        }
        const __nv_bfloat16 hv = __float2bfloat16(r);
        xsth[ob + c] = hv;
        xstl[ob + c] = __float2bfloat16(r - __bfloat162float(hv));
    }
}

// =========================================================================
extern "C" void kernel_launch(void* const* d_in, const int* in_sizes, int n_in,
                              void* d_out, int out_size)
{
    (void)in_sizes; (void)n_in; (void)out_size;

    const float* x1   = (const float*)d_in[0];
    const float* x2   = (const float*)d_in[1];
    const float* dw_w = (const float*)d_in[2];
    const float* dw_b = (const float*)d_in[3];
    const float* ln_g = (const float*)d_in[4];
    const float* ln_b = (const float*)d_in[5];
    const float* offw = (const float*)d_in[6];
    const float* wq   = (const float*)d_in[7];
    const float* bq   = (const float*)d_in[8];
    const float* wk   = (const float*)d_in[9];
    const float* bk   = (const float*)d_in[10];
    const float* wv   = (const float*)d_in[11];
    const float* bv   = (const float*)d_in[12];
    const float* wo   = (const float*)d_in[13];
    const float* bo   = (const float*)d_in[14];

    float* out  = (float*)d_out;
    float* attn = out + (ll)Bv * Sv * Cv;

    cudaFuncSetAttribute(mma_gemm, cudaFuncAttributeMaxDynamicSharedMemorySize, MMA_SMEM);
    cudaFuncSetAttribute(logits_mma, cudaFuncAttributeMaxDynamicSharedMemorySize, LSMEM);
    cudaFuncSetAttribute(offset_kernel, cudaFuncAttributeMaxDynamicSharedMemorySize, OFF_SMEM);

    void *p;
#define SYM(name, var) cudaGetSymbolAddress(&p, name); float* var = (float*)p;
#define SYMB(name, var) cudaGetSymbolAddress(&p, name); __nv_bfloat16* var = (__nv_bfloat16*)p;
    SYM(g_q2, pq2)  SYM(g_grid, pgrid)  SYM(g_rsum, prsum)
    SYMB(g_qh, qhp) SYMB(g_ql, qlp)
    SYMB(g_kh, khp) SYMB(g_kl, klp)
    SYMB(g_vh, vhp) SYMB(g_vl, vlp)
    SYMB(g_x1h, x1h)  SYMB(g_x1l, x1l)
    SYMB(g_xsth, xsth) SYMB(g_xstl, xstl)
    SYMB(g_avth, avth) SYMB(g_avtl, avtl)
    SYMB(g_wqh, wqh) SYMB(g_wql, wql)
    SYMB(g_wkh, wkh) SYMB(g_wkl, wkl)
    SYMB(g_wvh, wvh) SYMB(g_wvl, wvl)
    SYMB(g_woh, woh) SYMB(g_wol, wol)
#undef SYM
#undef SYMB

    const int NW = Cv * Cv;
    const int NX = Nv * Cv;
    const dim3 thr(256);

    // ---- splits (weights in one launch) + x1
    split4_bf16<<<dim3((NW + 255) / 256, 4), thr>>>(
        wq, wk, wv, wo, wqh, wql, wkh, wkl, wvh, wvl, woh, wol, NW);
    split_bf16<<<(NX + 255) / 256, thr>>>(x1, x1h, x1l, NX);

    // ---- q = wq @ x1^T : (C, Nv) fp32 + hi/lo
    mma_gemm<<<dim3(Nv / 128, Cv / 128, 1), thr, MMA_SMEM>>>(
        wqh, wql, wqh, wql, x1h, x1l, pq2, qhp, qlp, qhp, qlp,
        Cv, Nv, bq, bq, nullptr);

    // ---- offsets + sampling (hi/lo out)
    offset_kernel<<<dim3(Hv, Bv * Gv), thr, OFF_SMEM>>>(
        pq2, dw_w, dw_b, ln_g, ln_b, offw, pgrid);
    sample_kernel<<<dim3(Sv, Bv), thr>>>(x2, pgrid, xsth, xstl);

    // ---- k and v in ONE launch (z selects)
    mma_gemm<<<dim3(Nv / 128, Cv / 128, 2), thr, MMA_SMEM>>>(
        wkh, wkl, wvh, wvl, xsth, xstl, nullptr, khp, klp, vhp, vlp,
        Cv, Nv, bk, bv, nullptr);

    // ---- logits: exp(QK^T * scale) -> attn + per-CTA row sums
    logits_mma<<<dim3(7, Bv * NHv), thr, LSMEM>>>(qhp, qlp, khp, klp, attn, prsum);

    // ---- AV + normalize (pipelined): attn /= rsum (written back), avt = P.V
    av_mma<<<dim3(7, Bv * NHv), thr>>>(attn, prsum, vhp, vlp, avth, avtl);

    // ---- out = avt @ wo^T + bo -> d_out (Nv, C)
    mma_gemm<<<dim3(Cv / 128, Nv / 128, 1), thr, MMA_SMEM>>>(
        avth, avtl, avth, avtl, woh, wol, out, nullptr, nullptr, nullptr, nullptr,
        Cv, Cv, nullptr, nullptr, bo);
}

// round 11
// speedup vs baseline: 1.0863x; 1.0116x over previous
#include <cuda_runtime.h>
#include <cuda_bf16.h>
#include <math.h>
#include <stdint.h>

#define Bv   8
#define Cv   768
#define Hv   28
#define Wv   28
#define Gv   6
#define GCv  128
#define NHv  12
#define HCv  64
#define Sv   784
#define Nv   (Bv * Sv)      // 6272
#define SCALEv 0.125f
#define EPSv 1e-5f
#define PADE 4096

typedef long long ll;

// ---------------- scratch (device globals; no allocation) ----------------
__device__ float g_q2 [Cv * Nv];                       // (768, 6272) fp32 (offset path)
__device__ float g_grid[Bv * Gv * Sv * 2];
__device__ float g_rsum[Bv * NHv * Sv];                // softmax row sums

__device__ __nv_bfloat16 g_qh [Cv * Nv + PADE], g_ql [Cv * Nv + PADE];   // (C, Nv)
__device__ __nv_bfloat16 g_kh [Cv * Nv + PADE], g_kl [Cv * Nv + PADE];
__device__ __nv_bfloat16 g_vh [Cv * Nv + PADE], g_vl [Cv * Nv + PADE];
__device__ __nv_bfloat16 g_x1h [Nv * Cv], g_x1l [Nv * Cv];               // (Nv, C)
__device__ __nv_bfloat16 g_xsth[Nv * Cv], g_xstl[Nv * Cv];
__device__ __nv_bfloat16 g_avth[Nv * Cv], g_avtl[Nv * Cv];
__device__ __nv_bfloat16 g_wqh [Cv * Cv], g_wql [Cv * Cv];
__device__ __nv_bfloat16 g_wkh [Cv * Cv], g_wkl [Cv * Cv];
__device__ __nv_bfloat16 g_wvh [Cv * Cv], g_wvl [Cv * Cv];
__device__ __nv_bfloat16 g_woh [Cv * Cv], g_wol [Cv * Cv];

// ======================= PTX helpers (sm_80-portable) =====================
__device__ __forceinline__ uint32_t smem_u32(const void* p) {
    uint32_t a;
    asm("{ .reg .u64 t; cvta.to.shared.u64 t, %1; cvt.u32.u64 %0, t; }" : "=r"(a) : "l"(p));
    return a;
}
__device__ __forceinline__ void cpa16(uint32_t dst, const void* src) {
    asm volatile("cp.async.cg.shared.global [%0], [%1], 16;" :: "r"(dst), "l"(src));
}
#define CP_COMMIT() asm volatile("cp.async.commit_group;" ::: "memory")
#define CP_WAIT1()  asm volatile("cp.async.wait_group 1;" ::: "memory")
#define CP_WAIT0()  asm volatile("cp.async.wait_group 0;" ::: "memory")

__device__ __forceinline__ void ldsm4(uint32_t* r, uint32_t addr) {
    asm volatile("ldmatrix.sync.aligned.m8n8.x4.shared.b16 {%0,%1,%2,%3}, [%4];"
        : "=r"(r[0]), "=r"(r[1]), "=r"(r[2]), "=r"(r[3]) : "r"(addr));
}
__device__ __forceinline__ void ldsm4t(uint32_t* r, uint32_t addr) {
    asm volatile("ldmatrix.sync.aligned.m8n8.x4.trans.shared.b16 {%0,%1,%2,%3}, [%4];"
        : "=r"(r[0]), "=r"(r[1]), "=r"(r[2]), "=r"(r[3]) : "r"(addr));
}
__device__ __forceinline__ void mma16816(float* c, const uint32_t* a, const uint32_t* b) {
    asm volatile(
        "mma.sync.aligned.m16n8k16.row.col.f32.bf16.bf16.f32 "
        "{%0,%1,%2,%3}, {%4,%5,%6,%7}, {%8,%9}, {%0,%1,%2,%3};"
        : "+f"(c[0]), "+f"(c[1]), "+f"(c[2]), "+f"(c[3])
        : "r"(a[0]), "r"(a[1]), "r"(a[2]), "r"(a[3]), "r"(b[0]), "r"(b[1]));
}
__device__ __forceinline__ void store_hilo(__nv_bfloat16* Hp, __nv_bfloat16* Lp,
                                           ll idx, float a, float b) {
    const __nv_bfloat16 ha = __float2bfloat16(a), hb = __float2bfloat16(b);
    __nv_bfloat162 hv; hv.x = ha; hv.y = hb;
    *(__nv_bfloat162*)(Hp + idx) = hv;
    __nv_bfloat162 lv;
    lv.x = __float2bfloat16(a - __bfloat162float(ha));
    lv.y = __float2bfloat16(b - __bfloat162float(hb));
    *(__nv_bfloat162*)(Lp + idx) = lv;
}

// =========================================================================
// bf16x3 warp-MMA GEMM (dual-set via blockIdx.z):
//   C[M x N] = A(MxK) . B(NxK)^T (+bias_m +bias_n)
// =========================================================================
#define KC       32
#define TPAD     40
#define TILE_B   (128 * TPAD * 2)
#define STAGE_B  (4 * TILE_B)
#define MMA_SMEM (2 * STAGE_B)

__global__ void __launch_bounds__(256, 2)
mma_gemm(const __nv_bfloat16* __restrict__ Ah, const __nv_bfloat16* __restrict__ Al,
         const __nv_bfloat16* __restrict__ Ah2, const __nv_bfloat16* __restrict__ Al2,
         const __nv_bfloat16* __restrict__ Bh, const __nv_bfloat16* __restrict__ Bl,
         float* __restrict__ Cf,
         __nv_bfloat16* __restrict__ Chi, __nv_bfloat16* __restrict__ Clo,
         __nv_bfloat16* __restrict__ Chi2, __nv_bfloat16* __restrict__ Clo2,
         int K, int ldc,
         const float* __restrict__ bias_m, const float* __restrict__ bias_m2,
         const float* __restrict__ bias_n)
{
    if (blockIdx.z == 1) {
        Ah = Ah2; Al = Al2; Chi = Chi2; Clo = Clo2; bias_m = bias_m2; Cf = nullptr;
    }
    extern __shared__ char smem[];
    const uint32_t sb = smem_u32(smem);
    const int tid = threadIdx.x;
    const int wid = tid >> 5, lane = tid & 31;

    const int m0 = blockIdx.y * 128;
    const int n0 = blockIdx.x * 128;

    const __nv_bfloat16* srcs[4] = {
        Ah + (ll)m0 * K, Al + (ll)m0 * K,
        Bh + (ll)n0 * K, Bl + (ll)n0 * K };

    const int NCk = K / KC;

    float acc[2][8][4];
#pragma unroll
    for (int i = 0; i < 2; i++)
#pragma unroll
        for (int j = 0; j < 8; j++)
#pragma unroll
            for (int r = 0; r < 4; r++) acc[i][j][r] = 0.f;

    auto issue = [&](int c) {
        const uint32_t st = sb + (uint32_t)(c & 1) * STAGE_B;
        const ll kb = (ll)c * KC;
#pragma unroll
        for (int t = 0; t < 4; t++) {
            const __nv_bfloat16* src = srcs[t];
            const uint32_t tb = st + t * TILE_B;
#pragma unroll
            for (int it = 0; it < 2; it++) {
                const int idx = tid + it * 256;
                const int row = idx >> 2;
                const int q   = idx & 3;
                cpa16(tb + row * 80 + q * 16, src + (ll)row * K + kb + q * 8);
            }
        }
    };

    issue(0); CP_COMMIT();

    const int wm = (wid & 3) * 32;
    const int wn = (wid >> 2) * 64;
    const int rsel = lane & 7;
    const int aRow = wm + rsel + ((lane >> 3) & 1) * 8;
    const int aColB = ((lane >> 4) & 1) * 16;
    const int bRow = wn + rsel + ((lane >> 4) & 1) * 8;
    const int bColB = ((lane >> 3) & 1) * 16;

    for (int c = 0; c < NCk; c++) {
        if (c + 1 < NCk) issue(c + 1);
        CP_COMMIT();
        CP_WAIT1();
        __syncthreads();

        const uint32_t st = sb + (uint32_t)(c & 1) * STAGE_B;
#pragma unroll
        for (int kst = 0; kst < 2; kst++) {
            uint32_t ah[2][4], al[2][4];
#pragma unroll
            for (int mf = 0; mf < 2; mf++) {
                const uint32_t ra = st + (aRow + mf * 16) * 80 + kst * 32 + aColB;
                ldsm4(ah[mf], ra);
                ldsm4(al[mf], ra + TILE_B);
            }
            uint32_t bh[8][2], bl[8][2];
#pragma unroll
            for (int nf2 = 0; nf2 < 4; nf2++) {
                const uint32_t rb = st + 2 * TILE_B + (bRow + nf2 * 16) * 80 + kst * 32 + bColB;
                uint32_t t4[4];
                ldsm4(t4, rb);
                bh[nf2 * 2][0] = t4[0]; bh[nf2 * 2][1] = t4[1];
                bh[nf2 * 2 + 1][0] = t4[2]; bh[nf2 * 2 + 1][1] = t4[3];
                ldsm4(t4, rb + TILE_B);
                bl[nf2 * 2][0] = t4[0]; bl[nf2 * 2][1] = t4[1];
                bl[nf2 * 2 + 1][0] = t4[2]; bl[nf2 * 2 + 1][1] = t4[3];
            }
#pragma unroll
            for (int mf = 0; mf < 2; mf++)
#pragma unroll
                for (int nf = 0; nf < 8; nf++) {
                    mma16816(acc[mf][nf], ah[mf], bh[nf]);
                    mma16816(acc[mf][nf], ah[mf], bl[nf]);
                    mma16816(acc[mf][nf], al[mf], bh[nf]);
                }
        }
        __syncthreads();
    }

#pragma unroll
    for (int mf = 0; mf < 2; mf++) {
        const int r0 = m0 + wm + mf * 16 + (lane >> 2);
        const int r1 = r0 + 8;
        const float bm0 = bias_m ? __ldg(&bias_m[r0]) : 0.f;
        const float bm1 = bias_m ? __ldg(&bias_m[r1]) : 0.f;
#pragma unroll
        for (int nf = 0; nf < 8; nf++) {
            const int col = n0 + wn + nf * 8 + (lane & 3) * 2;
            float bn0 = 0.f, bn1 = 0.f;
            if (bias_n) { bn0 = __ldg(&bias_n[col]); bn1 = __ldg(&bias_n[col + 1]); }
            const float* a = acc[mf][nf];
            const float v00 = a[0] + bm0 + bn0, v01 = a[1] + bm0 + bn1;
            const float v10 = a[2] + bm1 + bn0, v11 = a[3] + bm1 + bn1;
            const ll i0 = (ll)r0 * ldc + col;
            const ll i1 = (ll)r1 * ldc + col;
            if (Cf) {
                float2 f0; f0.x = v00; f0.y = v01; *(float2*)&Cf[i0] = f0;
                float2 f1; f1.x = v10; f1.y = v11; *(float2*)&Cf[i1] = f1;
            }
            if (Chi) {
                store_hilo(Chi, Clo, i0, v00, v01);
                store_hilo(Chi, Clo, i1, v10, v11);
            }
        }
    }
}

// =========================================================================
// fp32 -> bf16 hi/lo split (single) and 4-way weight split
// =========================================================================
__global__ __launch_bounds__(256)
void split_bf16(const float* __restrict__ in, __nv_bfloat16* __restrict__ hi,
                __nv_bfloat16* __restrict__ lo, int n)
{
    const int i = blockIdx.x * 256 + threadIdx.x;
    if (i < n) {
        const float x = in[i];
        const __nv_bfloat16 h = __float2bfloat16(x);
        hi[i] = h;
        lo[i] = __float2bfloat16(x - __bfloat162float(h));
    }
}

__global__ __launch_bounds__(256)
void split4_bf16(const float* __restrict__ w0, const float* __restrict__ w1,
                 const float* __restrict__ w2, const float* __restrict__ w3,
                 __nv_bfloat16* __restrict__ h0, __nv_bfloat16* __restrict__ l0,
                 __nv_bfloat16* __restrict__ h1, __nv_bfloat16* __restrict__ l1,
                 __nv_bfloat16* __restrict__ h2, __nv_bfloat16* __restrict__ l2,
                 __nv_bfloat16* __restrict__ h3, __nv_bfloat16* __restrict__ l3,
                 int n)
{
    const int i = blockIdx.x * 256 + threadIdx.x;
    if (i >= n) return;
    const int s = blockIdx.y;
    const float* in = (s == 0) ? w0 : (s == 1) ? w1 : (s == 2) ? w2 : w3;
    __nv_bfloat16* hi = (s == 0) ? h0 : (s == 1) ? h1 : (s == 2) ? h2 : h3;
    __nv_bfloat16* lo = (s == 0) ? l0 : (s == 1) ? l1 : (s == 2) ? l2 : l3;
    const float x = in[i];
    const __nv_bfloat16 h = __float2bfloat16(x);
    hi[i] = h;
    lo[i] = __float2bfloat16(x - __bfloat162float(h));
}

// =========================================================================
// Logits (Q-resident, K-streamed): one CTA per (bh, 128-row i-tile).
// =========================================================================
#define LROWB 272
#define LT    17408
#define LSK   (2 * LT)
#define LSMEM (6 * LT)

__global__ void __launch_bounds__(256, 1)
logits_mma(const __nv_bfloat16* __restrict__ qh, const __nv_bfloat16* __restrict__ ql,
           const __nv_bfloat16* __restrict__ kh, const __nv_bfloat16* __restrict__ kl,
           float* __restrict__ attn, float* __restrict__ rsum)
{
    extern __shared__ char smem[];
    __shared__ float srow[128];
    const uint32_t sb = smem_u32(smem);
    const int tid = threadIdx.x;
    const int wid = tid >> 5, lane = tid & 31;
    const int bh = blockIdx.y, b = bh / NHv, h = bh % NHv;
    const int i0 = blockIdx.x * 128;

    if (tid < 128) srow[tid] = 0.f;

    const ll off = (ll)(h * HCv) * Nv + (ll)b * Sv;
    const __nv_bfloat16* q0 = qh + off + i0;
    const __nv_bfloat16* q1 = ql + off + i0;
    const __nv_bfloat16* k0 = kh + off;
    const __nv_bfloat16* k1 = kl + off;

#pragma unroll
    for (int it = 0; it < 4; it++) {
        const int idx = tid + it * 256;
        const int row = idx >> 4, q = idx & 15;
        cpa16(sb + row * LROWB + q * 16, q0 + (ll)row * Nv + q * 8);
        cpa16(sb + LT + row * LROWB + q * 16, q1 + (ll)row * Nv + q * 8);
    }
    CP_COMMIT();

    auto issueK = [&](int jc) {
        const uint32_t st = sb + LSK + (uint32_t)(jc & 1) * (2 * LT);
        const ll jb = (ll)jc * 128;
#pragma unroll
        for (int it = 0; it < 4; it++) {
            const int idx = tid + it * 256;
            const int row = idx >> 4, q = idx & 15;
            const ll go = (ll)row * Nv + jb + q * 8;
            cpa16(st + row * LROWB + q * 16, k0 + go);
            cpa16(st + LT + row * LROWB + q * 16, k1 + go);
        }
    };
    issueK(0); CP_COMMIT();

    const int wm = (wid & 3) * 32;
    const int wn = (wid >> 2) * 64;
    const int arowk = (lane & 7) + ((lane >> 4) & 1) * 8;
    const int acolm = wm + ((lane >> 3) & 1) * 8;
    const int browk = (lane & 7) + ((lane >> 3) & 1) * 8;
    const int bcoln = wn + ((lane >> 4) & 1) * 8;
    const int cb2 = (lane & 3) * 2;

    float* Cp = attn + (ll)bh * Sv * Sv;
    float rs[2][2] = {{0.f, 0.f}, {0.f, 0.f}};

    for (int jc = 0; jc < 7; jc++) {
        if (jc + 1 < 7) { issueK(jc + 1); CP_COMMIT(); CP_WAIT1(); }
        else           { CP_WAIT0(); }
        __syncthreads();

        const uint32_t sKh = sb + LSK + (uint32_t)(jc & 1) * (2 * LT);

        float acc[2][8][4];
#pragma unroll
        for (int i = 0; i < 2; i++)
#pragma unroll
            for (int j = 0; j < 8; j++)
#pragma unroll
                for (int r = 0; r < 4; r++) acc[i][j][r] = 0.f;

#pragma unroll
        for (int kst = 0; kst < 4; kst++) {
            uint32_t ah[2][4], al[2][4];
#pragma unroll
            for (int mf = 0; mf < 2; mf++) {
                const uint32_t ra = sb + (kst * 16 + arowk) * LROWB + (acolm + mf * 16) * 2;
                ldsm4t(ah[mf], ra);
                ldsm4t(al[mf], ra + LT);
            }
            uint32_t bhf[8][2], blf[8][2];
#pragma unroll
            for (int nf2 = 0; nf2 < 4; nf2++) {
                const uint32_t rb = sKh + (kst * 16 + browk) * LROWB + (bcoln + nf2 * 16) * 2;
                uint32_t t4[4];
                ldsm4t(t4, rb);
                bhf[nf2 * 2][0] = t4[0]; bhf[nf2 * 2][1] = t4[1];
                bhf[nf2 * 2 + 1][0] = t4[2]; bhf[nf2 * 2 + 1][1] = t4[3];
                ldsm4t(t4, rb + LT);
                blf[nf2 * 2][0] = t4[0]; blf[nf2 * 2][1] = t4[1];
                blf[nf2 * 2 + 1][0] = t4[2]; blf[nf2 * 2 + 1][1] = t4[3];
            }
#pragma unroll
            for (int mf = 0; mf < 2; mf++)
#pragma unroll
                for (int nf = 0; nf < 8; nf++) {
                    mma16816(acc[mf][nf], ah[mf], bhf[nf]);
                    mma16816(acc[mf][nf], ah[mf], blf[nf]);
                    mma16816(acc[mf][nf], al[mf], bhf[nf]);
                }
        }

        const int j0 = jc * 128;
#pragma unroll
        for (int mf = 0; mf < 2; mf++) {
            const int r0 = i0 + wm + mf * 16 + (lane >> 2);
            const int r1 = r0 + 8;
#pragma unroll
            for (int nf = 0; nf < 8; nf++) {
                const int col = j0 + wn + nf * 8 + cb2;
                if (col >= Sv) continue;
                const float* a = acc[mf][nf];
                if (r0 < Sv) {
                    float2 f;
                    f.x = __expf(a[0] * SCALEv);
                    f.y = __expf(a[1] * SCALEv);
                    *(float2*)&Cp[(ll)r0 * Sv + col] = f;
                    rs[mf][0] += f.x + f.y;
                }
                if (r1 < Sv) {
                    float2 f;
                    f.x = __expf(a[2] * SCALEv);
                    f.y = __expf(a[3] * SCALEv);
                    *(float2*)&Cp[(ll)r1 * Sv + col] = f;
                    rs[mf][1] += f.x + f.y;
                }
            }
        }
        __syncthreads();
    }

#pragma unroll
    for (int mf = 0; mf < 2; mf++) {
        float s0 = rs[mf][0], s1 = rs[mf][1];
        s0 += __shfl_xor_sync(0xffffffffu, s0, 1);
        s0 += __shfl_xor_sync(0xffffffffu, s0, 2);
        s1 += __shfl_xor_sync(0xffffffffu, s1, 1);
        s1 += __shfl_xor_sync(0xffffffffu, s1, 2);
        if ((lane & 3) == 0) {
            const int lr = wm + mf * 16 + (lane >> 2);
            atomicAdd(&srow[lr], s0);
            atomicAdd(&srow[lr + 8], s1);
        }
    }
    __syncthreads();
    if (tid < 128 && i0 + tid < Sv)
        rsum[(ll)bh * Sv + i0 + tid] = srow[tid];
}

// =========================================================================
// AV + softmax-normalize (pipelined)
// =========================================================================
#define AVROWB 80
#define AV_A_H   0
#define AV_A_L   10240
#define AV_B     20480
#define AV_SMEMB (20480 + 2 * 10240)

__global__ void __launch_bounds__(256, 1)
av_mma(float* __restrict__ attn, const float* __restrict__ rsum,
       const __nv_bfloat16* __restrict__ vh, const __nv_bfloat16* __restrict__ vl,
       __nv_bfloat16* __restrict__ avth, __nv_bfloat16* __restrict__ avtl)
{
    __shared__ char smc[AV_SMEMB];
    __shared__ float sm_inv[128];
    const uint32_t sb = smem_u32(smc);

    const int tid = threadIdx.x;
    const int wid = tid >> 5, lane = tid & 31;
    const int bh = blockIdx.y, b = bh / NHv, h = bh % NHv;
    const int n0 = blockIdx.x * 128;

    float* Ap = attn + (ll)bh * Sv * Sv;
    const __nv_bfloat16* vbh = vh + (ll)(h * HCv) * Nv + (ll)b * Sv;
    const __nv_bfloat16* vbl = vl + (ll)(h * HCv) * Nv + (ll)b * Sv;

    if (tid < 128) {
        const int gn = n0 + tid;
        sm_inv[tid] = (gn < Sv) ? (1.f / rsum[(ll)bh * Sv + gn]) : 0.f;
    }
    __syncthreads();

    float acc[2][4][4];
#pragma unroll
    for (int i = 0; i < 2; i++)
#pragma unroll
        for (int j = 0; j < 4; j++)
#pragma unroll
            for (int r = 0; r < 4; r++) acc[i][j][r] = 0.f;

    const int wm = (wid & 3) * 32;
    const int wn = (wid >> 2) * 32;
    const int rsel = lane & 7;
    const int aRow = wm + rsel + ((lane >> 3) & 1) * 8;
    const int aColB = ((lane >> 4) & 1) * 16;
    const int bRow = wn + rsel + ((lane >> 4) & 1) * 8;
    const int bColB = ((lane >> 3) & 1) * 16;

    const int vrow = tid >> 2;
    const int vq   = tid & 3;

    float4 areg[4];

    auto issueB = [&](int kc) {
        const int kb = kc * 32;
        const uint32_t bb = sb + AV_B + (uint32_t)(kc & 1) * 10240;
        cpa16(bb + vrow * AVROWB + vq * 16, vbh + (ll)vrow * Nv + kb + vq * 8);
        cpa16(bb + 5120 + vrow * AVROWB + vq * 16, vbl + (ll)vrow * Nv + kb + vq * 8);
    };
    auto loadA = [&](int kc) {
        const int kb = kc * 32;
#pragma unroll
        for (int it = 0; it < 4; it++) {
            const int idx4 = tid + it * 256;
            const int row = idx4 >> 3;
            const int qq  = idx4 & 7;
            const int gn = n0 + row;
            const int gk = kb + qq * 4;
            areg[it] = make_float4(0.f, 0.f, 0.f, 0.f);
            if (gn < Sv && gk < Sv)
                areg[it] = *(const float4*)&Ap[(ll)gn * Sv + gk];
        }
    };

    issueB(0); CP_COMMIT();
    loadA(0);

    for (int kc = 0; kc < 25; kc++) {
        const int kb = kc * 32;
#pragma unroll
        for (int it = 0; it < 4; it++) {
            const int idx4 = tid + it * 256;
            const int row = idx4 >> 3;
            const int qq  = idx4 & 7;
            const int gn = n0 + row;
            const int gk = kb + qq * 4;
            float4 v = areg[it];
            const float inv = sm_inv[row];
            v.x *= inv; v.y *= inv; v.z *= inv; v.w *= inv;
            if (gn < Sv && gk < Sv) *(float4*)&Ap[(ll)gn * Sv + gk] = v;
            const __nv_bfloat16 h0 = __float2bfloat16(v.x), h1 = __float2bfloat16(v.y);
            const __nv_bfloat16 h2 = __float2bfloat16(v.z), h3 = __float2bfloat16(v.w);
            __nv_bfloat162 p01, p23, q01, q23;
            p01.x = h0; p01.y = h1; p23.x = h2; p23.y = h3;
            q01.x = __float2bfloat16(v.x - __bfloat162float(h0));
            q01.y = __float2bfloat16(v.y - __bfloat162float(h1));
            q23.x = __float2bfloat16(v.z - __bfloat162float(h2));
            q23.y = __float2bfloat16(v.w - __bfloat162float(h3));
            uint2 hw, lw;
            hw.x = *(uint32_t*)&p01; hw.y = *(uint32_t*)&p23;
            lw.x = *(uint32_t*)&q01; lw.y = *(uint32_t*)&q23;
            *(uint2*)(smc + AV_A_H + row * AVROWB + qq * 8) = hw;
            *(uint2*)(smc + AV_A_L + row * AVROWB + qq * 8) = lw;
        }
        if (kc + 1 < 25) {
            issueB(kc + 1); CP_COMMIT();
            loadA(kc + 1);
            CP_WAIT1();
        } else {
            CP_WAIT0();
        }
        __syncthreads();

        const uint32_t sBh = sb + AV_B + (uint32_t)(kc & 1) * 10240;
        const uint32_t sAh = sb + AV_A_H;
#pragma unroll
        for (int kst = 0; kst < 2; kst++) {
            uint32_t ah[2][4], al[2][4];
#pragma unroll
            for (int mf = 0; mf < 2; mf++) {
                const uint32_t ra = sAh + (aRow + mf * 16) * AVROWB + kst * 32 + aColB;
                ldsm4(ah[mf], ra);
                ldsm4(al[mf], ra + (AV_A_L - AV_A_H));
            }
            uint32_t bhf[4][2], blf[4][2];
#pragma unroll
            for (int nf2 = 0; nf2 < 2; nf2++) {
                const uint32_t rb = sBh + (bRow + nf2 * 16) * AVROWB + kst * 32 + bColB;
                uint32_t t4[4];
                ldsm4(t4, rb);
                bhf[nf2 * 2][0] = t4[0]; bhf[nf2 * 2][1] = t4[1];
                bhf[nf2 * 2 + 1][0] = t4[2]; bhf[nf2 * 2 + 1][1] = t4[3];
                ldsm4(t4, rb + 5120);
                blf[nf2 * 2][0] = t4[0]; blf[nf2 * 2][1] = t4[1];
                blf[nf2 * 2 + 1][0] = t4[2]; blf[nf2 * 2 + 1][1] = t4[3];
            }
#pragma unroll
            for (int mf = 0; mf < 2; mf++)
#pragma unroll
                for (int nf = 0; nf < 4; nf++) {
                    mma16816(acc[mf][nf], ah[mf], bhf[nf]);
                    mma16816(acc[mf][nf], ah[mf], blf[nf]);
                    mma16816(acc[mf][nf], al[mf], bhf[nf]);
                }
        }
        __syncthreads();
    }

#pragma unroll
    for (int mf = 0; mf < 2; mf++) {
        const int r0 = n0 + wm + mf * 16 + (lane >> 2);
        const int r1 = r0 + 8;
#pragma unroll
        for (int nf = 0; nf < 4; nf++) {
            const int cold = wn + nf * 8 + (lane & 3) * 2;
            const ll colg = (ll)h * HCv + cold;
            const float* a = acc[mf][nf];
            if (r0 < Sv)
                store_hilo(avth, avtl, ((ll)b * Sv + r0) * Cv + colg, a[0], a[1]);
            if (r1 < Sv)
                store_hilo(avth, avtl, ((ll)b * Sv + r1) * Cv + colg, a[2], a[3]);
        }
    }
}

// =========================================================================
// Fused dwconv5x5 -> LN -> GELU -> offset proj -> sampling coords
// 4 h-rows per CTA; inputs staged in smem (coalesced float4), register
// sliding-window conv.
// =========================================================================
#define OHv 4
#define OFF_QS   (8 * GCv * Wv)
#define OFF_TS   (OHv * GCv * Wv)
#define OFF_SMEM ((OFF_QS + OFF_TS) * 4)   // 172032 B

__global__ void __launch_bounds__(256)
offset_kernel(const float* __restrict__ q2,
              const float* __restrict__ dw_w,
              const float* __restrict__ dw_b,
              const float* __restrict__ ln_g,
              const float* __restrict__ ln_b,
              const float* __restrict__ off_w,
              float* __restrict__ gridbuf)
{
    extern __shared__ float dsm[];
    float* qs = dsm;                 // [8][128][28]
    float* ts = dsm + OFF_QS;        // [OHv][128][28]
    __shared__ float ssum[OHv * Wv * 2], ssq[OHv * Wv * 2];
    __shared__ float s_mean[OHv * Wv], s_rstd[OHv * Wv];

    const int h0 = blockIdx.x * OHv;
    const int bg = blockIdx.y;
    const int b = bg / Gv, g = bg % Gv;
    const int tid = threadIdx.x;

    const float* qbase = q2 + (ll)(g * GCv) * Nv + b * Sv;

    // ---- stage 8 padded rows x 128 channels, coalesced float4
    for (int idx = tid; idx < 8 * GCv * 7; idx += 256) {
        const int xq = idx % 7;
        const int t  = idx / 7;
        const int c  = t & 127;
        const int r  = t >> 7;
        const int hh = h0 + r - 2;
        float4 v = make_float4(0.f, 0.f, 0.f, 0.f);
        if (hh >= 0 && hh < Hv)
            v = *(const float4*)&qbase[(ll)c * Nv + hh * Wv + xq * 4];
        *(float4*)&qs[(r * GCv + c) * Wv + xq * 4] = v;
    }
    __syncthreads();

    // ---- conv from smem, register sliding window, OHv output rows
    {
        const int c  = tid >> 1;
        const int xh = tid & 1;
        const int x0 = xh * 14;
        const float* wrow = dw_w + c * 25;
        const float bc = dw_b[c];

#pragma unroll
        for (int hl = 0; hl < OHv; hl++) {
            float acc[14];
#pragma unroll
            for (int i = 0; i < 14; i++) acc[i] = bc;

#pragma unroll
            for (int dy = 0; dy < 5; dy++) {
                const float* row = &qs[((hl + dy) * GCv + c) * Wv];
                float r[18];
                if (xh == 0) {
                    r[0] = 0.f; r[1] = 0.f;
#pragma unroll
                    for (int j = 2; j < 18; j++) r[j] = row[j - 2];
                } else {
#pragma unroll
                    for (int j = 0; j < 16; j++) r[j] = row[12 + j];
                    r[16] = 0.f; r[17] = 0.f;
                }
#pragma unroll
                for (int dx = 0; dx < 5; dx++) {
                    const float w = wrow[dy * 5 + dx];
#pragma unroll
                    for (int i = 0; i < 14; i++)
                        acc[i] = fmaf(w, r[i + dx], acc[i]);
                }
            }
#pragma unroll
            for (int i = 0; i < 14; i++)
                ts[hl * GCv * Wv + c * Wv + x0 + i] = acc[i];
        }
    }
    __syncthreads();

    // ---- LN stats: 224 threads = (hl, part, x); each sums 64 channels
    if (tid < OHv * Wv * 2) {
        const int x  = tid % Wv;
        const int pp = (tid / Wv) & 1;
        const int hl = tid / (Wv * 2);
        const float* tb = ts + hl * GCv * Wv;
        float s = 0.f, sq = 0.f;
        for (int c = pp * 64; c < pp * 64 + 64; c++) {
            const float v = tb[c * Wv + x];
            s += v; sq += v * v;
        }
        ssum[tid] = s; ssq[tid] = sq;
    }
    __syncthreads();
    if (tid < OHv * Wv) {
        const int x  = tid % Wv;
        const int hl = tid / Wv;
        const int b0 = hl * Wv * 2 + x;
        const float s  = ssum[b0] + ssum[b0 + Wv];
        const float sq = ssq[b0]  + ssq[b0 + Wv];
        const float mu  = s * (1.f / GCv);
        const float var = sq * (1.f / GCv) - mu * mu;
        s_mean[tid] = mu;
        s_rstd[tid] = rsqrtf(var + EPSv);
    }
    __syncthreads();

    // ---- normalize + GELU
    for (int idx = tid; idx < OHv * GCv * Wv; idx += 256) {
        const int x  = idx % Wv;
        const int t  = idx / Wv;
        const int c  = t & 127;
        const int hl = t >> 7;
        const int o  = (hl * GCv + c) * Wv + x;
        const float vv = (ts[o] - s_mean[hl * Wv + x]) * s_rstd[hl * Wv + x]
                         * ln_g[c] + ln_b[c];
        ts[o] = 0.5f * vv * (1.f + erff(vv * 0.70710678118654752f));
    }
    __syncthreads();

    // ---- offset projection: 224 threads = (o, hl, x)
    if (tid < 2 * OHv * Wv) {
        const int x  = tid % Wv;
        const int hl = (tid / Wv) % OHv;
        const int o  = tid / (Wv * OHv);
        const int h  = h0 + hl;
        float s = 0.f;
        const float* w = off_w + o * GCv;
        const float* tb = ts + hl * GCv * Wv;
        for (int c = 0; c < GCv; c++) s += w[c] * tb[c * Wv + x];
        const float off = tanhf(s) * (2.0f / 28.0f);
        const float ref = (float)(2 * (o == 0 ? h : x) + 1) * (1.0f / 28.0f) - 1.0f;
        const float pix = ((off + ref) + 1.0f) * 0.5f * 27.0f;
        gridbuf[((ll)bg * Sv + h * Wv + x) * 2 + (o == 0 ? 1 : 0)] = pix;
    }
}

// =========================================================================
// Bilinear gather -> xst hi/lo (Nv, C)
// =========================================================================
__global__ __launch_bounds__(256)
void sample_kernel(const float* __restrict__ x2,
                   const float* __restrict__ gridbuf,
                   __nv_bfloat16* __restrict__ xsth,
                   __nv_bfloat16* __restrict__ xstl)
{
    const int p = blockIdx.x;
    const int b = blockIdx.y;
    const int tid = threadIdx.x;

    __shared__ float coords[Gv][2];
    if (tid < Gv * 2) {
        const int g = tid >> 1, o = tid & 1;
        coords[g][o] = gridbuf[((ll)(b * Gv + g) * Sv + p) * 2 + o];
    }
    __syncthreads();

    const float* xb = x2 + (ll)b * Sv * Cv;
    const ll ob = ((ll)b * Sv + p) * Cv;

    for (int c = tid; c < Cv; c += 256) {
        const int g = c >> 7;
        const float px = coords[g][0], py = coords[g][1];
        const float x0f = floorf(px), y0f = floorf(py);
        const int x0 = (int)x0f, y0 = (int)y0f;
        const float wx1 = px - x0f, wy1 = py - y0f;
        const float wx0 = 1.f - wx1, wy0 = 1.f - wy1;

        float r = 0.f;
#pragma unroll
        for (int dy = 0; dy < 2; dy++) {
            const int yy = y0 + dy;
            if (yy < 0 || yy >= Hv) continue;
            const float wy = dy ? wy1 : wy0;
#pragma unroll
            for (int dx = 0; dx < 2; dx++) {
                const int xx = x0 + dx;
                if (xx < 0 || xx >= Wv) continue;
                const float wx = dx ? wx1 : wx0;
                r += wy * wx * __ldg(&xb[(ll)(yy * Wv + xx) * Cv + c]);
            }
        }
        const __nv_bfloat16 hv = __float2bfloat16(r);
        xsth[ob + c] = hv;
        xstl[ob + c] = __float2bfloat16(r - __bfloat162float(hv));
    }
}

// =========================================================================
extern "C" void kernel_launch(void* const* d_in, const int* in_sizes, int n_in,
                              void* d_out, int out_size)
{
    (void)in_sizes; (void)n_in; (void)out_size;

    const float* x1   = (const float*)d_in[0];
    const float* x2   = (const float*)d_in[1];
    const float* dw_w = (const float*)d_in[2];
    const float* dw_b = (const float*)d_in[3];
    const float* ln_g = (const float*)d_in[4];
    const float* ln_b = (const float*)d_in[5];
    const float* offw = (const float*)d_in[6];
    const float* wq   = (const float*)d_in[7];
    const float* bq   = (const float*)d_in[8];
    const float* wk   = (const float*)d_in[9];
    const float* bk   = (const float*)d_in[10];
    const float* wv   = (const float*)d_in[11];
    const float* bv   = (const float*)d_in[12];
    const float* wo   = (const float*)d_in[13];
    const float* bo   = (const float*)d_in[14];

    float* out  = (float*)d_out;
    float* attn = out + (ll)Bv * Sv * Cv;

    cudaFuncSetAttribute(mma_gemm, cudaFuncAttributeMaxDynamicSharedMemorySize, MMA_SMEM);
    cudaFuncSetAttribute(logits_mma, cudaFuncAttributeMaxDynamicSharedMemorySize, LSMEM);
    cudaFuncSetAttribute(offset_kernel, cudaFuncAttributeMaxDynamicSharedMemorySize, OFF_SMEM);

    void *p;
#define SYM(name, var) cudaGetSymbolAddress(&p, name); float* var = (float*)p;
#define SYMB(name, var) cudaGetSymbolAddress(&p, name); __nv_bfloat16* var = (__nv_bfloat16*)p;
    SYM(g_q2, pq2)  SYM(g_grid, pgrid)  SYM(g_rsum, prsum)
    SYMB(g_qh, qhp) SYMB(g_ql, qlp)
    SYMB(g_kh, khp) SYMB(g_kl, klp)
    SYMB(g_vh, vhp) SYMB(g_vl, vlp)
    SYMB(g_x1h, x1h)  SYMB(g_x1l, x1l)
    SYMB(g_xsth, xsth) SYMB(g_xstl, xstl)
    SYMB(g_avth, avth) SYMB(g_avtl, avtl)
    SYMB(g_wqh, wqh) SYMB(g_wql, wql)
    SYMB(g_wkh, wkh) SYMB(g_wkl, wkl)
    SYMB(g_wvh, wvh) SYMB(g_wvl, wvl)
    SYMB(g_woh, woh) SYMB(g_wol, wol)
#undef SYM
#undef SYMB

    const int NW = Cv * Cv;
    const int NX = Nv * Cv;
    const dim3 thr(256);

    // ---- splits (weights in one launch) + x1
    split4_bf16<<<dim3((NW + 255) / 256, 4), thr>>>(
        wq, wk, wv, wo, wqh, wql, wkh, wkl, wvh, wvl, woh, wol, NW);
    split_bf16<<<(NX + 255) / 256, thr>>>(x1, x1h, x1l, NX);

    // ---- q = wq @ x1^T : (C, Nv) fp32 + hi/lo
    mma_gemm<<<dim3(Nv / 128, Cv / 128, 1), thr, MMA_SMEM>>>(
        wqh, wql, wqh, wql, x1h, x1l, pq2, qhp, qlp, qhp, qlp,
        Cv, Nv, bq, bq, nullptr);

    // ---- offsets + sampling (hi/lo out)
    offset_kernel<<<dim3(Hv / OHv, Bv * Gv), thr, OFF_SMEM>>>(
        pq2, dw_w, dw_b, ln_g, ln_b, offw, pgrid);
    sample_kernel<<<dim3(Sv, Bv), thr>>>(x2, pgrid, xsth, xstl);

    // ---- k and v in ONE launch (z selects)
    mma_gemm<<<dim3(Nv / 128, Cv / 128, 2), thr, MMA_SMEM>>>(
        wkh, wkl, wvh, wvl, xsth, xstl, nullptr, khp, klp, vhp, vlp,
        Cv, Nv, bk, bv, nullptr);

    // ---- logits: exp(QK^T * scale) -> attn + per-CTA row sums
    logits_mma<<<dim3(7, Bv * NHv), thr, LSMEM>>>(qhp, qlp, khp, klp, attn, prsum);

    // ---- AV + normalize (pipelined): attn /= rsum (written back), avt = P.V
    av_mma<<<dim3(7, Bv * NHv), thr>>>(attn, prsum, vhp, vlp, avth, avtl);

    // ---- out = avt @ wo^T + bo -> d_out (Nv, C)
    mma_gemm<<<dim3(Cv / 128, Nv / 128, 1), thr, MMA_SMEM>>>(
        avth, avtl, avth, avtl, woh, wol, out, nullptr, nullptr, nullptr, nullptr,
        Cv, Cv, nullptr, nullptr, bo);
}

// round 12
// speedup vs baseline: 1.1006x; 1.0131x over previous
#include <cuda_runtime.h>
#include <cuda_bf16.h>
#include <math.h>
#include <stdint.h>

#define Bv   8
#define Cv   768
#define Hv   28
#define Wv   28
#define Gv   6
#define GCv  128
#define NHv  12
#define HCv  64
#define Sv   784
#define Nv   (Bv * Sv)      // 6272
#define SCALEv 0.125f
#define EPSv 1e-5f
#define PADE 4096

typedef long long ll;

// ---------------- scratch (device globals; no allocation) ----------------
__device__ float g_q2 [Cv * Nv];                       // (768, 6272) fp32 (offset path)
__device__ float g_grid[Bv * Gv * Sv * 2];
__device__ float g_rsum[Bv * NHv * Sv];                // softmax row sums

__device__ __nv_bfloat16 g_qh [Cv * Nv + PADE], g_ql [Cv * Nv + PADE];   // (C, Nv)
__device__ __nv_bfloat16 g_kh [Cv * Nv + PADE], g_kl [Cv * Nv + PADE];
__device__ __nv_bfloat16 g_vh [Cv * Nv + PADE], g_vl [Cv * Nv + PADE];
__device__ __nv_bfloat16 g_x1h [Nv * Cv], g_x1l [Nv * Cv];               // (Nv, C)
__device__ __nv_bfloat16 g_xsth[Nv * Cv], g_xstl[Nv * Cv];
__device__ __nv_bfloat16 g_avth[Nv * Cv], g_avtl[Nv * Cv];
__device__ __nv_bfloat16 g_wqh [Cv * Cv], g_wql [Cv * Cv];
__device__ __nv_bfloat16 g_wkh [Cv * Cv], g_wkl [Cv * Cv];
__device__ __nv_bfloat16 g_wvh [Cv * Cv], g_wvl [Cv * Cv];
__device__ __nv_bfloat16 g_woh [Cv * Cv], g_wol [Cv * Cv];

// ======================= PTX helpers (sm_80-portable) =====================
__device__ __forceinline__ uint32_t smem_u32(const void* p) {
    uint32_t a;
    asm("{ .reg .u64 t; cvta.to.shared.u64 t, %1; cvt.u32.u64 %0, t; }" : "=r"(a) : "l"(p));
    return a;
}
__device__ __forceinline__ void cpa16(uint32_t dst, const void* src) {
    asm volatile("cp.async.cg.shared.global [%0], [%1], 16;" :: "r"(dst), "l"(src));
}
#define CP_COMMIT() asm volatile("cp.async.commit_group;" ::: "memory")
#define CP_WAIT1()  asm volatile("cp.async.wait_group 1;" ::: "memory")
#define CP_WAIT0()  asm volatile("cp.async.wait_group 0;" ::: "memory")

__device__ __forceinline__ void ldsm4(uint32_t* r, uint32_t addr) {
    asm volatile("ldmatrix.sync.aligned.m8n8.x4.shared.b16 {%0,%1,%2,%3}, [%4];"
        : "=r"(r[0]), "=r"(r[1]), "=r"(r[2]), "=r"(r[3]) : "r"(addr));
}
__device__ __forceinline__ void ldsm4t(uint32_t* r, uint32_t addr) {
    asm volatile("ldmatrix.sync.aligned.m8n8.x4.trans.shared.b16 {%0,%1,%2,%3}, [%4];"
        : "=r"(r[0]), "=r"(r[1]), "=r"(r[2]), "=r"(r[3]) : "r"(addr));
}
__device__ __forceinline__ void mma16816(float* c, const uint32_t* a, const uint32_t* b) {
    asm volatile(
        "mma.sync.aligned.m16n8k16.row.col.f32.bf16.bf16.f32 "
        "{%0,%1,%2,%3}, {%4,%5,%6,%7}, {%8,%9}, {%0,%1,%2,%3};"
        : "+f"(c[0]), "+f"(c[1]), "+f"(c[2]), "+f"(c[3])
        : "r"(a[0]), "r"(a[1]), "r"(a[2]), "r"(a[3]), "r"(b[0]), "r"(b[1]));
}
__device__ __forceinline__ void store_hilo(__nv_bfloat16* Hp, __nv_bfloat16* Lp,
                                           ll idx, float a, float b) {
    const __nv_bfloat16 ha = __float2bfloat16(a), hb = __float2bfloat16(b);
    __nv_bfloat162 hv; hv.x = ha; hv.y = hb;
    *(__nv_bfloat162*)(Hp + idx) = hv;
    __nv_bfloat162 lv;
    lv.x = __float2bfloat16(a - __bfloat162float(ha));
    lv.y = __float2bfloat16(b - __bfloat162float(hb));
    *(__nv_bfloat162*)(Lp + idx) = lv;
}

// =========================================================================
// bf16x3 warp-MMA GEMM (dual-set via blockIdx.z):
//   C[M x N] = A(MxK) . B(NxK)^T (+bias_m +bias_n)
// =========================================================================
#define KC       32
#define TPAD     40
#define TILE_B   (128 * TPAD * 2)
#define STAGE_B  (4 * TILE_B)
#define MMA_SMEM (2 * STAGE_B)

__global__ void __launch_bounds__(256, 2)
mma_gemm(const __nv_bfloat16* __restrict__ Ah, const __nv_bfloat16* __restrict__ Al,
         const __nv_bfloat16* __restrict__ Ah2, const __nv_bfloat16* __restrict__ Al2,
         const __nv_bfloat16* __restrict__ Bh, const __nv_bfloat16* __restrict__ Bl,
         float* __restrict__ Cf,
         __nv_bfloat16* __restrict__ Chi, __nv_bfloat16* __restrict__ Clo,
         __nv_bfloat16* __restrict__ Chi2, __nv_bfloat16* __restrict__ Clo2,
         int K, int ldc,
         const float* __restrict__ bias_m, const float* __restrict__ bias_m2,
         const float* __restrict__ bias_n)
{
    if (blockIdx.z == 1) {
        Ah = Ah2; Al = Al2; Chi = Chi2; Clo = Clo2; bias_m = bias_m2; Cf = nullptr;
    }
    extern __shared__ char smem[];
    const uint32_t sb = smem_u32(smem);
    const int tid = threadIdx.x;
    const int wid = tid >> 5, lane = tid & 31;

    const int m0 = blockIdx.y * 128;
    const int n0 = blockIdx.x * 128;

    const __nv_bfloat16* srcs[4] = {
        Ah + (ll)m0 * K, Al + (ll)m0 * K,
        Bh + (ll)n0 * K, Bl + (ll)n0 * K };

    const int NCk = K / KC;

    float acc[2][8][4];
#pragma unroll
    for (int i = 0; i < 2; i++)
#pragma unroll
        for (int j = 0; j < 8; j++)
#pragma unroll
            for (int r = 0; r < 4; r++) acc[i][j][r] = 0.f;

    auto issue = [&](int c) {
        const uint32_t st = sb + (uint32_t)(c & 1) * STAGE_B;
        const ll kb = (ll)c * KC;
#pragma unroll
        for (int t = 0; t < 4; t++) {
            const __nv_bfloat16* src = srcs[t];
            const uint32_t tb = st + t * TILE_B;
#pragma unroll
            for (int it = 0; it < 2; it++) {
                const int idx = tid + it * 256;
                const int row = idx >> 2;
                const int q   = idx & 3;
                cpa16(tb + row * 80 + q * 16, src + (ll)row * K + kb + q * 8);
            }
        }
    };

    issue(0); CP_COMMIT();

    const int wm = (wid & 3) * 32;
    const int wn = (wid >> 2) * 64;
    const int rsel = lane & 7;
    const int aRow = wm + rsel + ((lane >> 3) & 1) * 8;
    const int aColB = ((lane >> 4) & 1) * 16;
    const int bRow = wn + rsel + ((lane >> 4) & 1) * 8;
    const int bColB = ((lane >> 3) & 1) * 16;

    for (int c = 0; c < NCk; c++) {
        if (c + 1 < NCk) issue(c + 1);
        CP_COMMIT();
        CP_WAIT1();
        __syncthreads();

        const uint32_t st = sb + (uint32_t)(c & 1) * STAGE_B;
#pragma unroll
        for (int kst = 0; kst < 2; kst++) {
            uint32_t ah[2][4], al[2][4];
#pragma unroll
            for (int mf = 0; mf < 2; mf++) {
                const uint32_t ra = st + (aRow + mf * 16) * 80 + kst * 32 + aColB;
                ldsm4(ah[mf], ra);
                ldsm4(al[mf], ra + TILE_B);
            }
            uint32_t bh[8][2], bl[8][2];
#pragma unroll
            for (int nf2 = 0; nf2 < 4; nf2++) {
                const uint32_t rb = st + 2 * TILE_B + (bRow + nf2 * 16) * 80 + kst * 32 + bColB;
                uint32_t t4[4];
                ldsm4(t4, rb);
                bh[nf2 * 2][0] = t4[0]; bh[nf2 * 2][1] = t4[1];
                bh[nf2 * 2 + 1][0] = t4[2]; bh[nf2 * 2 + 1][1] = t4[3];
                ldsm4(t4, rb + TILE_B);
                bl[nf2 * 2][0] = t4[0]; bl[nf2 * 2][1] = t4[1];
                bl[nf2 * 2 + 1][0] = t4[2]; bl[nf2 * 2 + 1][1] = t4[3];
            }
#pragma unroll
            for (int mf = 0; mf < 2; mf++)
#pragma unroll
                for (int nf = 0; nf < 8; nf++) {
                    mma16816(acc[mf][nf], ah[mf], bh[nf]);
                    mma16816(acc[mf][nf], ah[mf], bl[nf]);
                    mma16816(acc[mf][nf], al[mf], bh[nf]);
                }
        }
        __syncthreads();
    }

#pragma unroll
    for (int mf = 0; mf < 2; mf++) {
        const int r0 = m0 + wm + mf * 16 + (lane >> 2);
        const int r1 = r0 + 8;
        const float bm0 = bias_m ? __ldg(&bias_m[r0]) : 0.f;
        const float bm1 = bias_m ? __ldg(&bias_m[r1]) : 0.f;
#pragma unroll
        for (int nf = 0; nf < 8; nf++) {
            const int col = n0 + wn + nf * 8 + (lane & 3) * 2;
            float bn0 = 0.f, bn1 = 0.f;
            if (bias_n) { bn0 = __ldg(&bias_n[col]); bn1 = __ldg(&bias_n[col + 1]); }
            const float* a = acc[mf][nf];
            const float v00 = a[0] + bm0 + bn0, v01 = a[1] + bm0 + bn1;
            const float v10 = a[2] + bm1 + bn0, v11 = a[3] + bm1 + bn1;
            const ll i0 = (ll)r0 * ldc + col;
            const ll i1 = (ll)r1 * ldc + col;
            if (Cf) {
                float2 f0; f0.x = v00; f0.y = v01; *(float2*)&Cf[i0] = f0;
                float2 f1; f1.x = v10; f1.y = v11; *(float2*)&Cf[i1] = f1;
            }
            if (Chi) {
                store_hilo(Chi, Clo, i0, v00, v01);
                store_hilo(Chi, Clo, i1, v10, v11);
            }
        }
    }
}

// =========================================================================
// fp32 -> bf16 hi/lo split (single) and 4-way weight split
// =========================================================================
__global__ __launch_bounds__(256)
void split_bf16(const float* __restrict__ in, __nv_bfloat16* __restrict__ hi,
                __nv_bfloat16* __restrict__ lo, int n)
{
    const int i = blockIdx.x * 256 + threadIdx.x;
    if (i < n) {
        const float x = in[i];
        const __nv_bfloat16 h = __float2bfloat16(x);
        hi[i] = h;
        lo[i] = __float2bfloat16(x - __bfloat162float(h));
    }
}

__global__ __launch_bounds__(256)
void split4_bf16(const float* __restrict__ w0, const float* __restrict__ w1,
                 const float* __restrict__ w2, const float* __restrict__ w3,
                 __nv_bfloat16* __restrict__ h0, __nv_bfloat16* __restrict__ l0,
                 __nv_bfloat16* __restrict__ h1, __nv_bfloat16* __restrict__ l1,
                 __nv_bfloat16* __restrict__ h2, __nv_bfloat16* __restrict__ l2,
                 __nv_bfloat16* __restrict__ h3, __nv_bfloat16* __restrict__ l3,
                 int n)
{
    const int i = blockIdx.x * 256 + threadIdx.x;
    if (i >= n) return;
    const int s = blockIdx.y;
    const float* in = (s == 0) ? w0 : (s == 1) ? w1 : (s == 2) ? w2 : w3;
    __nv_bfloat16* hi = (s == 0) ? h0 : (s == 1) ? h1 : (s == 2) ? h2 : h3;
    __nv_bfloat16* lo = (s == 0) ? l0 : (s == 1) ? l1 : (s == 2) ? l2 : l3;
    const float x = in[i];
    const __nv_bfloat16 h = __float2bfloat16(x);
    hi[i] = h;
    lo[i] = __float2bfloat16(x - __bfloat162float(h));
}

// =========================================================================
// Logits (Q-resident, K-streamed): one CTA per (bh, 128-row i-tile).
// =========================================================================
#define LROWB 272
#define LT    17408
#define LSK   (2 * LT)
#define LSMEM (6 * LT)

__global__ void __launch_bounds__(256, 2)
logits_mma(const __nv_bfloat16* __restrict__ qh, const __nv_bfloat16* __restrict__ ql,
           const __nv_bfloat16* __restrict__ kh, const __nv_bfloat16* __restrict__ kl,
           float* __restrict__ attn, float* __restrict__ rsum)
{
    extern __shared__ char smem[];
    __shared__ float srow[128];
    const uint32_t sb = smem_u32(smem);
    const int tid = threadIdx.x;
    const int wid = tid >> 5, lane = tid & 31;
    const int bh = blockIdx.y, b = bh / NHv, h = bh % NHv;
    const int i0 = blockIdx.x * 128;

    if (tid < 128) srow[tid] = 0.f;

    const ll off = (ll)(h * HCv) * Nv + (ll)b * Sv;
    const __nv_bfloat16* q0 = qh + off + i0;
    const __nv_bfloat16* q1 = ql + off + i0;
    const __nv_bfloat16* k0 = kh + off;
    const __nv_bfloat16* k1 = kl + off;

#pragma unroll
    for (int it = 0; it < 4; it++) {
        const int idx = tid + it * 256;
        const int row = idx >> 4, q = idx & 15;
        cpa16(sb + row * LROWB + q * 16, q0 + (ll)row * Nv + q * 8);
        cpa16(sb + LT + row * LROWB + q * 16, q1 + (ll)row * Nv + q * 8);
    }
    CP_COMMIT();

    auto issueK = [&](int jc) {
        const uint32_t st = sb + LSK + (uint32_t)(jc & 1) * (2 * LT);
        const ll jb = (ll)jc * 128;
#pragma unroll
        for (int it = 0; it < 4; it++) {
            const int idx = tid + it * 256;
            const int row = idx >> 4, q = idx & 15;
            const ll go = (ll)row * Nv + jb + q * 8;
            cpa16(st + row * LROWB + q * 16, k0 + go);
            cpa16(st + LT + row * LROWB + q * 16, k1 + go);
        }
    };
    issueK(0); CP_COMMIT();

    const int wm = (wid & 3) * 32;
    const int wn = (wid >> 2) * 64;
    const int arowk = (lane & 7) + ((lane >> 4) & 1) * 8;
    const int acolm = wm + ((lane >> 3) & 1) * 8;
    const int browk = (lane & 7) + ((lane >> 3) & 1) * 8;
    const int bcoln = wn + ((lane >> 4) & 1) * 8;
    const int cb2 = (lane & 3) * 2;

    float* Cp = attn + (ll)bh * Sv * Sv;
    float rs[2][2] = {{0.f, 0.f}, {0.f, 0.f}};

    for (int jc = 0; jc < 7; jc++) {
        if (jc + 1 < 7) { issueK(jc + 1); CP_COMMIT(); CP_WAIT1(); }
        else           { CP_WAIT0(); }
        __syncthreads();

        const uint32_t sKh = sb + LSK + (uint32_t)(jc & 1) * (2 * LT);

        float acc[2][8][4];
#pragma unroll
        for (int i = 0; i < 2; i++)
#pragma unroll
            for (int j = 0; j < 8; j++)
#pragma unroll
                for (int r = 0; r < 4; r++) acc[i][j][r] = 0.f;

#pragma unroll
        for (int kst = 0; kst < 4; kst++) {
            uint32_t ah[2][4], al[2][4];
#pragma unroll
            for (int mf = 0; mf < 2; mf++) {
                const uint32_t ra = sb + (kst * 16 + arowk) * LROWB + (acolm + mf * 16) * 2;
                ldsm4t(ah[mf], ra);
                ldsm4t(al[mf], ra + LT);
            }
            uint32_t bhf[8][2], blf[8][2];
#pragma unroll
            for (int nf2 = 0; nf2 < 4; nf2++) {
                const uint32_t rb = sKh + (kst * 16 + browk) * LROWB + (bcoln + nf2 * 16) * 2;
                uint32_t t4[4];
                ldsm4t(t4, rb);
                bhf[nf2 * 2][0] = t4[0]; bhf[nf2 * 2][1] = t4[1];
                bhf[nf2 * 2 + 1][0] = t4[2]; bhf[nf2 * 2 + 1][1] = t4[3];
                ldsm4t(t4, rb + LT);
                blf[nf2 * 2][0] = t4[0]; blf[nf2 * 2][1] = t4[1];
                blf[nf2 * 2 + 1][0] = t4[2]; blf[nf2 * 2 + 1][1] = t4[3];
            }
#pragma unroll
            for (int mf = 0; mf < 2; mf++)
#pragma unroll
                for (int nf = 0; nf < 8; nf++) {
                    mma16816(acc[mf][nf], ah[mf], bhf[nf]);
                    mma16816(acc[mf][nf], ah[mf], blf[nf]);
                    mma16816(acc[mf][nf], al[mf], bhf[nf]);
                }
        }

        const int j0 = jc * 128;
#pragma unroll
        for (int mf = 0; mf < 2; mf++) {
            const int r0 = i0 + wm + mf * 16 + (lane >> 2);
            const int r1 = r0 + 8;
#pragma unroll
            for (int nf = 0; nf < 8; nf++) {
                const int col = j0 + wn + nf * 8 + cb2;
                if (col >= Sv) continue;
                const float* a = acc[mf][nf];
                if (r0 < Sv) {
                    float2 f;
                    f.x = __expf(a[0] * SCALEv);
                    f.y = __expf(a[1] * SCALEv);
                    *(float2*)&Cp[(ll)r0 * Sv + col] = f;
                    rs[mf][0] += f.x + f.y;
                }
                if (r1 < Sv) {
                    float2 f;
                    f.x = __expf(a[2] * SCALEv);
                    f.y = __expf(a[3] * SCALEv);
                    *(float2*)&Cp[(ll)r1 * Sv + col] = f;
                    rs[mf][1] += f.x + f.y;
                }
            }
        }
        __syncthreads();
    }

#pragma unroll
    for (int mf = 0; mf < 2; mf++) {
        float s0 = rs[mf][0], s1 = rs[mf][1];
        s0 += __shfl_xor_sync(0xffffffffu, s0, 1);
        s0 += __shfl_xor_sync(0xffffffffu, s0, 2);
        s1 += __shfl_xor_sync(0xffffffffu, s1, 1);
        s1 += __shfl_xor_sync(0xffffffffu, s1, 2);
        if ((lane & 3) == 0) {
            const int lr = wm + mf * 16 + (lane >> 2);
            atomicAdd(&srow[lr], s0);
            atomicAdd(&srow[lr + 8], s1);
        }
    }
    __syncthreads();
    if (tid < 128 && i0 + tid < Sv)
        rsum[(ll)bh * Sv + i0 + tid] = srow[tid];
}

// =========================================================================
// AV + softmax-normalize (pipelined)
// =========================================================================
#define AVROWB 80
#define AV_A_H   0
#define AV_A_L   10240
#define AV_B     20480
#define AV_SMEMB (20480 + 2 * 10240)

__global__ void __launch_bounds__(256, 2)
av_mma(float* __restrict__ attn, const float* __restrict__ rsum,
       const __nv_bfloat16* __restrict__ vh, const __nv_bfloat16* __restrict__ vl,
       __nv_bfloat16* __restrict__ avth, __nv_bfloat16* __restrict__ avtl)
{
    __shared__ char smc[AV_SMEMB];
    __shared__ float sm_inv[128];
    const uint32_t sb = smem_u32(smc);

    const int tid = threadIdx.x;
    const int wid = tid >> 5, lane = tid & 31;
    const int bh = blockIdx.y, b = bh / NHv, h = bh % NHv;
    const int n0 = blockIdx.x * 128;

    float* Ap = attn + (ll)bh * Sv * Sv;
    const __nv_bfloat16* vbh = vh + (ll)(h * HCv) * Nv + (ll)b * Sv;
    const __nv_bfloat16* vbl = vl + (ll)(h * HCv) * Nv + (ll)b * Sv;

    if (tid < 128) {
        const int gn = n0 + tid;
        sm_inv[tid] = (gn < Sv) ? (1.f / rsum[(ll)bh * Sv + gn]) : 0.f;
    }
    __syncthreads();

    float acc[2][4][4];
#pragma unroll
    for (int i = 0; i < 2; i++)
#pragma unroll
        for (int j = 0; j < 4; j++)
#pragma unroll
            for (int r = 0; r < 4; r++) acc[i][j][r] = 0.f;

    const int wm = (wid & 3) * 32;
    const int wn = (wid >> 2) * 32;
    const int rsel = lane & 7;
    const int aRow = wm + rsel + ((lane >> 3) & 1) * 8;
    const int aColB = ((lane >> 4) & 1) * 16;
    const int bRow = wn + rsel + ((lane >> 4) & 1) * 8;
    const int bColB = ((lane >> 3) & 1) * 16;

    const int vrow = tid >> 2;
    const int vq   = tid & 3;

    float4 areg[4];

    auto issueB = [&](int kc) {
        const int kb = kc * 32;
        const uint32_t bb = sb + AV_B + (uint32_t)(kc & 1) * 10240;
        cpa16(bb + vrow * AVROWB + vq * 16, vbh + (ll)vrow * Nv + kb + vq * 8);
        cpa16(bb + 5120 + vrow * AVROWB + vq * 16, vbl + (ll)vrow * Nv + kb + vq * 8);
    };
    auto loadA = [&](int kc) {
        const int kb = kc * 32;
#pragma unroll
        for (int it = 0; it < 4; it++) {
            const int idx4 = tid + it * 256;
            const int row = idx4 >> 3;
            const int qq  = idx4 & 7;
            const int gn = n0 + row;
            const int gk = kb + qq * 4;
            areg[it] = make_float4(0.f, 0.f, 0.f, 0.f);
            if (gn < Sv && gk < Sv)
                areg[it] = *(const float4*)&Ap[(ll)gn * Sv + gk];
        }
    };

    issueB(0); CP_COMMIT();
    loadA(0);

    for (int kc = 0; kc < 25; kc++) {
        const int kb = kc * 32;
#pragma unroll
        for (int it = 0; it < 4; it++) {
            const int idx4 = tid + it * 256;
            const int row = idx4 >> 3;
            const int qq  = idx4 & 7;
            const int gn = n0 + row;
            const int gk = kb + qq * 4;
            float4 v = areg[it];
            const float inv = sm_inv[row];
            v.x *= inv; v.y *= inv; v.z *= inv; v.w *= inv;
            if (gn < Sv && gk < Sv) *(float4*)&Ap[(ll)gn * Sv + gk] = v;
            const __nv_bfloat16 h0 = __float2bfloat16(v.x), h1 = __float2bfloat16(v.y);
            const __nv_bfloat16 h2 = __float2bfloat16(v.z), h3 = __float2bfloat16(v.w);
            __nv_bfloat162 p01, p23, q01, q23;
            p01.x = h0; p01.y = h1; p23.x = h2; p23.y = h3;
            q01.x = __float2bfloat16(v.x - __bfloat162float(h0));
            q01.y = __float2bfloat16(v.y - __bfloat162float(h1));
            q23.x = __float2bfloat16(v.z - __bfloat162float(h2));
            q23.y = __float2bfloat16(v.w - __bfloat162float(h3));
            uint2 hw, lw;
            hw.x = *(uint32_t*)&p01; hw.y = *(uint32_t*)&p23;
            lw.x = *(uint32_t*)&q01; lw.y = *(uint32_t*)&q23;
            *(uint2*)(smc + AV_A_H + row * AVROWB + qq * 8) = hw;
            *(uint2*)(smc + AV_A_L + row * AVROWB + qq * 8) = lw;
        }
        if (kc + 1 < 25) {
            issueB(kc + 1); CP_COMMIT();
            loadA(kc + 1);
            CP_WAIT1();
        } else {
            CP_WAIT0();
        }
        __syncthreads();

        const uint32_t sBh = sb + AV_B + (uint32_t)(kc & 1) * 10240;
        const uint32_t sAh = sb + AV_A_H;
#pragma unroll
        for (int kst = 0; kst < 2; kst++) {
            uint32_t ah[2][4], al[2][4];
#pragma unroll
            for (int mf = 0; mf < 2; mf++) {
                const uint32_t ra = sAh + (aRow + mf * 16) * AVROWB + kst * 32 + aColB;
                ldsm4(ah[mf], ra);
                ldsm4(al[mf], ra + (AV_A_L - AV_A_H));
            }
            uint32_t bhf[4][2], blf[4][2];
#pragma unroll
            for (int nf2 = 0; nf2 < 2; nf2++) {
                const uint32_t rb = sBh + (bRow + nf2 * 16) * AVROWB + kst * 32 + bColB;
                uint32_t t4[4];
                ldsm4(t4, rb);
                bhf[nf2 * 2][0] = t4[0]; bhf[nf2 * 2][1] = t4[1];
                bhf[nf2 * 2 + 1][0] = t4[2]; bhf[nf2 * 2 + 1][1] = t4[3];
                ldsm4(t4, rb + 5120);
                blf[nf2 * 2][0] = t4[0]; blf[nf2 * 2][1] = t4[1];
                blf[nf2 * 2 + 1][0] = t4[2]; blf[nf2 * 2 + 1][1] = t4[3];
            }
#pragma unroll
            for (int mf = 0; mf < 2; mf++)
#pragma unroll
                for (int nf = 0; nf < 4; nf++) {
                    mma16816(acc[mf][nf], ah[mf], bhf[nf]);
                    mma16816(acc[mf][nf], ah[mf], blf[nf]);
                    mma16816(acc[mf][nf], al[mf], bhf[nf]);
                }
        }
        __syncthreads();
    }

#pragma unroll
    for (int mf = 0; mf < 2; mf++) {
        const int r0 = n0 + wm + mf * 16 + (lane >> 2);
        const int r1 = r0 + 8;
#pragma unroll
        for (int nf = 0; nf < 4; nf++) {
            const int cold = wn + nf * 8 + (lane & 3) * 2;
            const ll colg = (ll)h * HCv + cold;
            const float* a = acc[mf][nf];
            if (r0 < Sv)
                store_hilo(avth, avtl, ((ll)b * Sv + r0) * Cv + colg, a[0], a[1]);
            if (r1 < Sv)
                store_hilo(avth, avtl, ((ll)b * Sv + r1) * Cv + colg, a[2], a[3]);
        }
    }
}

// =========================================================================
// Fused dwconv5x5 -> LN -> GELU -> offset proj -> sampling coords
// 4 h-rows per CTA; inputs staged in smem (coalesced float4), register
// sliding-window conv.
// =========================================================================
#define OHv 4
#define OFF_QS   (8 * GCv * Wv)
#define OFF_TS   (OHv * GCv * Wv)
#define OFF_SMEM ((OFF_QS + OFF_TS) * 4)   // 172032 B

__global__ void __launch_bounds__(256)
offset_kernel(const float* __restrict__ q2,
              const float* __restrict__ dw_w,
              const float* __restrict__ dw_b,
              const float* __restrict__ ln_g,
              const float* __restrict__ ln_b,
              const float* __restrict__ off_w,
              float* __restrict__ gridbuf)
{
    extern __shared__ float dsm[];
    float* qs = dsm;                 // [8][128][28]
    float* ts = dsm + OFF_QS;        // [OHv][128][28]
    __shared__ float ssum[OHv * Wv * 2], ssq[OHv * Wv * 2];
    __shared__ float s_mean[OHv * Wv], s_rstd[OHv * Wv];

    const int h0 = blockIdx.x * OHv;
    const int bg = blockIdx.y;
    const int b = bg / Gv, g = bg % Gv;
    const int tid = threadIdx.x;

    const float* qbase = q2 + (ll)(g * GCv) * Nv + b * Sv;

    // ---- stage 8 padded rows x 128 channels, coalesced float4
    for (int idx = tid; idx < 8 * GCv * 7; idx += 256) {
        const int xq = idx % 7;
        const int t  = idx / 7;
        const int c  = t & 127;
        const int r  = t >> 7;
        const int hh = h0 + r - 2;
        float4 v = make_float4(0.f, 0.f, 0.f, 0.f);
        if (hh >= 0 && hh < Hv)
            v = *(const float4*)&qbase[(ll)c * Nv + hh * Wv + xq * 4];
        *(float4*)&qs[(r * GCv + c) * Wv + xq * 4] = v;
    }
    __syncthreads();

    // ---- conv from smem, register sliding window, OHv output rows
    {
        const int c  = tid >> 1;
        const int xh = tid & 1;
        const int x0 = xh * 14;
        const float* wrow = dw_w + c * 25;
        const float bc = dw_b[c];

#pragma unroll
        for (int hl = 0; hl < OHv; hl++) {
            float acc[14];
#pragma unroll
            for (int i = 0; i < 14; i++) acc[i] = bc;

#pragma unroll
            for (int dy = 0; dy < 5; dy++) {
                const float* row = &qs[((hl + dy) * GCv + c) * Wv];
                float r[18];
                if (xh == 0) {
                    r[0] = 0.f; r[1] = 0.f;
#pragma unroll
                    for (int j = 2; j < 18; j++) r[j] = row[j - 2];
                } else {
#pragma unroll
                    for (int j = 0; j < 16; j++) r[j] = row[12 + j];
                    r[16] = 0.f; r[17] = 0.f;
                }
#pragma unroll
                for (int dx = 0; dx < 5; dx++) {
                    const float w = wrow[dy * 5 + dx];
#pragma unroll
                    for (int i = 0; i < 14; i++)
                        acc[i] = fmaf(w, r[i + dx], acc[i]);
                }
            }
#pragma unroll
            for (int i = 0; i < 14; i++)
                ts[hl * GCv * Wv + c * Wv + x0 + i] = acc[i];
        }
    }
    __syncthreads();

    // ---- LN stats: 224 threads = (hl, part, x); each sums 64 channels
    if (tid < OHv * Wv * 2) {
        const int x  = tid % Wv;
        const int pp = (tid / Wv) & 1;
        const int hl = tid / (Wv * 2);
        const float* tb = ts + hl * GCv * Wv;
        float s = 0.f, sq = 0.f;
        for (int c = pp * 64; c < pp * 64 + 64; c++) {
            const float v = tb[c * Wv + x];
            s += v; sq += v * v;
        }
        ssum[tid] = s; ssq[tid] = sq;
    }
    __syncthreads();
    if (tid < OHv * Wv) {
        const int x  = tid % Wv;
        const int hl = tid / Wv;
        const int b0 = hl * Wv * 2 + x;
        const float s  = ssum[b0] + ssum[b0 + Wv];
        const float sq = ssq[b0]  + ssq[b0 + Wv];
        const float mu  = s * (1.f / GCv);
        const float var = sq * (1.f / GCv) - mu * mu;
        s_mean[tid] = mu;
        s_rstd[tid] = rsqrtf(var + EPSv);
    }
    __syncthreads();

    // ---- normalize + GELU
    for (int idx = tid; idx < OHv * GCv * Wv; idx += 256) {
        const int x  = idx % Wv;
        const int t  = idx / Wv;
        const int c  = t & 127;
        const int hl = t >> 7;
        const int o  = (hl * GCv + c) * Wv + x;
        const float vv = (ts[o] - s_mean[hl * Wv + x]) * s_rstd[hl * Wv + x]
                         * ln_g[c] + ln_b[c];
        ts[o] = 0.5f * vv * (1.f + erff(vv * 0.70710678118654752f));
    }
    __syncthreads();

    // ---- offset projection: 224 threads = (o, hl, x)
    if (tid < 2 * OHv * Wv) {
        const int x  = tid % Wv;
        const int hl = (tid / Wv) % OHv;
        const int o  = tid / (Wv * OHv);
        const int h  = h0 + hl;
        float s = 0.f;
        const float* w = off_w + o * GCv;
        const float* tb = ts + hl * GCv * Wv;
        for (int c = 0; c < GCv; c++) s += w[c] * tb[c * Wv + x];
        const float off = tanhf(s) * (2.0f / 28.0f);
        const float ref = (float)(2 * (o == 0 ? h : x) + 1) * (1.0f / 28.0f) - 1.0f;
        const float pix = ((off + ref) + 1.0f) * 0.5f * 27.0f;
        gridbuf[((ll)bg * Sv + h * Wv + x) * 2 + (o == 0 ? 1 : 0)] = pix;
    }
}

// =========================================================================
// Bilinear gather -> xst hi/lo (Nv, C)
// =========================================================================
__global__ __launch_bounds__(256)
void sample_kernel(const float* __restrict__ x2,
                   const float* __restrict__ gridbuf,
                   __nv_bfloat16* __restrict__ xsth,
                   __nv_bfloat16* __restrict__ xstl)
{
    const int p = blockIdx.x;
    const int b = blockIdx.y;
    const int tid = threadIdx.x;

    __shared__ float coords[Gv][2];
    if (tid < Gv * 2) {
        const int g = tid >> 1, o = tid & 1;
        coords[g][o] = gridbuf[((ll)(b * Gv + g) * Sv + p) * 2 + o];
    }
    __syncthreads();

    const float* xb = x2 + (ll)b * Sv * Cv;
    const ll ob = ((ll)b * Sv + p) * Cv;

    for (int c = tid; c < Cv; c += 256) {
        const int g = c >> 7;
        const float px = coords[g][0], py = coords[g][1];
        const float x0f = floorf(px), y0f = floorf(py);
        const int x0 = (int)x0f, y0 = (int)y0f;
        const float wx1 = px - x0f, wy1 = py - y0f;
        const float wx0 = 1.f - wx1, wy0 = 1.f - wy1;

        float r = 0.f;
#pragma unroll
        for (int dy = 0; dy < 2; dy++) {
            const int yy = y0 + dy;
            if (yy < 0 || yy >= Hv) continue;
            const float wy = dy ? wy1 : wy0;
#pragma unroll
            for (int dx = 0; dx < 2; dx++) {
                const int xx = x0 + dx;
                if (xx < 0 || xx >= Wv) continue;
                const float wx = dx ? wx1 : wx0;
                r += wy * wx * __ldg(&xb[(ll)(yy * Wv + xx) * Cv + c]);
            }
        }
        const __nv_bfloat16 hv = __float2bfloat16(r);
        xsth[ob + c] = hv;
        xstl[ob + c] = __float2bfloat16(r - __bfloat162float(hv));
    }
}

// =========================================================================
extern "C" void kernel_launch(void* const* d_in, const int* in_sizes, int n_in,
                              void* d_out, int out_size)
{
    (void)in_sizes; (void)n_in; (void)out_size;

    const float* x1   = (const float*)d_in[0];
    const float* x2   = (const float*)d_in[1];
    const float* dw_w = (const float*)d_in[2];
    const float* dw_b = (const float*)d_in[3];
    const float* ln_g = (const float*)d_in[4];
    const float* ln_b = (const float*)d_in[5];
    const float* offw = (const float*)d_in[6];
    const float* wq   = (const float*)d_in[7];
    const float* bq   = (const float*)d_in[8];
    const float* wk   = (const float*)d_in[9];
    const float* bk   = (const float*)d_in[10];
    const float* wv   = (const float*)d_in[11];
    const float* bv   = (const float*)d_in[12];
    const float* wo   = (const float*)d_in[13];
    const float* bo   = (const float*)d_in[14];

    float* out  = (float*)d_out;
    float* attn = out + (ll)Bv * Sv * Cv;

    cudaFuncSetAttribute(mma_gemm, cudaFuncAttributeMaxDynamicSharedMemorySize, MMA_SMEM);
    cudaFuncSetAttribute(logits_mma, cudaFuncAttributeMaxDynamicSharedMemorySize, LSMEM);
    cudaFuncSetAttribute(offset_kernel, cudaFuncAttributeMaxDynamicSharedMemorySize, OFF_SMEM);

    void *p;
#define SYM(name, var) cudaGetSymbolAddress(&p, name); float* var = (float*)p;
#define SYMB(name, var) cudaGetSymbolAddress(&p, name); __nv_bfloat16* var = (__nv_bfloat16*)p;
    SYM(g_q2, pq2)  SYM(g_grid, pgrid)  SYM(g_rsum, prsum)
    SYMB(g_qh, qhp) SYMB(g_ql, qlp)
    SYMB(g_kh, khp) SYMB(g_kl, klp)
    SYMB(g_vh, vhp) SYMB(g_vl, vlp)
    SYMB(g_x1h, x1h)  SYMB(g_x1l, x1l)
    SYMB(g_xsth, xsth) SYMB(g_xstl, xstl)
    SYMB(g_avth, avth) SYMB(g_avtl, avtl)
    SYMB(g_wqh, wqh) SYMB(g_wql, wql)
    SYMB(g_wkh, wkh) SYMB(g_wkl, wkl)
    SYMB(g_wvh, wvh) SYMB(g_wvl, wvl)
    SYMB(g_woh, woh) SYMB(g_wol, wol)
#undef SYM
#undef SYMB

    const int NW = Cv * Cv;
    const int NX = Nv * Cv;
    const dim3 thr(256);

    // ---- splits (weights in one launch) + x1
    split4_bf16<<<dim3((NW + 255) / 256, 4), thr>>>(
        wq, wk, wv, wo, wqh, wql, wkh, wkl, wvh, wvl, woh, wol, NW);
    split_bf16<<<(NX + 255) / 256, thr>>>(x1, x1h, x1l, NX);

    // ---- q = wq @ x1^T : (C, Nv) fp32 + hi/lo
    mma_gemm<<<dim3(Nv / 128, Cv / 128, 1), thr, MMA_SMEM>>>(
        wqh, wql, wqh, wql, x1h, x1l, pq2, qhp, qlp, qhp, qlp,
        Cv, Nv, bq, bq, nullptr);

    // ---- offsets + sampling (hi/lo out)
    offset_kernel<<<dim3(Hv / OHv, Bv * Gv), thr, OFF_SMEM>>>(
        pq2, dw_w, dw_b, ln_g, ln_b, offw, pgrid);
    sample_kernel<<<dim3(Sv, Bv), thr>>>(x2, pgrid, xsth, xstl);

    // ---- k and v in ONE launch (z selects)
    mma_gemm<<<dim3(Nv / 128, Cv / 128, 2), thr, MMA_SMEM>>>(
        wkh, wkl, wvh, wvl, xsth, xstl, nullptr, khp, klp, vhp, vlp,
        Cv, Nv, bk, bv, nullptr);

    // ---- logits: exp(QK^T * scale) -> attn + per-CTA row sums
    logits_mma<<<dim3(7, Bv * NHv), thr, LSMEM>>>(qhp, qlp, khp, klp, attn, prsum);

    // ---- AV + normalize (pipelined): attn /= rsum (written back), avt = P.V
    av_mma<<<dim3(7, Bv * NHv), thr>>>(attn, prsum, vhp, vlp, avth, avtl);

    // ---- out = avt @ wo^T + bo -> d_out (Nv, C)
    mma_gemm<<<dim3(Cv / 128, Nv / 128, 1), thr, MMA_SMEM>>>(
        avth, avtl, avth, avtl, woh, wol, out, nullptr, nullptr, nullptr, nullptr,
        Cv, Cv, nullptr, nullptr, bo);
}